// round 5
// baseline (speedup 1.0000x reference)
#include <cuda_runtime.h>

constexpr int C_ = 64, K_ = 48, MQ_MAX = 25000, NSLOT = 8, KSTR = 66;

// kernel1 smem offsets (floats)
constexpr int O_WQT=0, O_WK=4096, O_WVT=8192, O_BQ=12288, O_BV=12352,
  O_QPW=12416, O_QPB=12608, O_KPW=12672, O_KPB=12864, O_SLOT=12928;
constexpr int S_KIN=0, S_U=3168, S_QV=3424, S_QIN=3488, S_SB=3552, S_CTX=3744,
  S_REL=4004, S_MSK=4148, S_KIX=4196, S_QC=4244, S_INV=4248, SLOT_FL=4256;
constexpr int SMEM1_BYTES = (O_SLOT + NSLOT*SLOT_FL) * 4;   // 187904

// kernel2 smem offsets (floats)
constexpr int Q_WOT=0, Q_W1T=4096, Q_W2T=20480, Q_WOUT=36864, Q_BO=40960,
  Q_B1=41024, Q_B2=41280, Q_BN1S=41344, Q_BN1T=41408, Q_BN2S=41472,
  Q_BN2T=41536, Q_OUTB=41600, Q_GRP=41664, GRP_FL=1536;
constexpr int SMEM2_BYTES = (Q_GRP + 4*GRP_FL) * 4;         // 191232

__device__ float g_obuf[MQ_MAX * C_];

// Block-local detection of key_mask storage: 0=uint8, 1=int32, 2=float32.
// 512 threads scan the first 4096 bytes (mask buffer is >= 1.2MB in any dtype).
// Deterministic: same input bytes -> same mode, every block, every call.
__device__ __forceinline__ int detect_mask_mode(const unsigned char* __restrict__ b,
                                                int* scratch, int tid) {
    unsigned my123 = 0, my3f = 0;
    #pragma unroll
    for (int j = 0; j < 8; j++) {
        int i = tid * 8 + j;
        unsigned v = b[i];
        if ((i & 3) && v) my123 = 1;             // nonzero byte off word boundary
        if ((i & 3) == 3 && v == 0x3fu) my3f = 1; // 1.0f exponent byte
    }
    unsigned w123 = __ballot_sync(0xffffffffu, my123 != 0);
    unsigned w3f  = __ballot_sync(0xffffffffu, my3f  != 0);
    if ((tid & 31) == 0) {
        scratch[(tid >> 5) * 2 + 0] = (w123 != 0);
        scratch[(tid >> 5) * 2 + 1] = (w3f  != 0);
    }
    __syncthreads();
    if (tid == 0) {
        int a123 = 0, a3f = 0;
        for (int w = 0; w < 16; w++) { a123 |= scratch[w*2]; a3f |= scratch[w*2+1]; }
        scratch[32] = (a123 == 0) ? 1 : (a3f ? 2 : 0);
    }
    __syncthreads();
    int mode = scratch[32];
    __syncthreads();   // scratch region (slot smem) reused by main loop
    return mode;
}

// ============================================================================
// Kernel 1: gather + pos-proj + restructured MHA -> g_obuf
// ============================================================================
__global__ __launch_bounds__(512, 1) void attn_kernel(
    const float* __restrict__ vf, const float* __restrict__ vcoord,
    const float* __restrict__ qcoord, const int* __restrict__ kidx,
    const void* __restrict__ kmask,
    const float* __restrict__ qpw_g, const float* __restrict__ qpb_g,
    const float* __restrict__ kpw_g, const float* __restrict__ kpb_g,
    const float* __restrict__ ipW, const float* __restrict__ ipB, int m)
{
    extern __shared__ float sm[];
    const int tid = threadIdx.x;

    for (int i = tid; i < 4096; i += 512) {
        int c = i & 63, cp = i >> 6;
        sm[O_WQT + i] = ipW[c * 64 + cp];           // wq^T
        sm[O_WK  + i] = ipW[4096 + i];              // wk row-major
        sm[O_WVT + i] = ipW[(128 + c) * 64 + cp];   // wv^T
    }
    if (tid < 64) {
        sm[O_BQ + tid] = ipB[tid];
        sm[O_BV + tid] = ipB[128 + tid];
        sm[O_QPB + tid] = qpb_g[tid];
        sm[O_KPB + tid] = kpb_g[tid];
    }
    if (tid < 192) { sm[O_QPW + tid] = qpw_g[tid]; sm[O_KPW + tid] = kpw_g[tid]; }
    __syncthreads();

    const int mode = detect_mask_mode((const unsigned char*)kmask,
                                      (int*)(sm + O_SLOT), tid);

    const int slot = tid >> 6, lane = tid & 63;
    float* S = sm + O_SLOT + slot * SLOT_FL;
    float* kin = S + S_KIN;  float* u_s = S + S_U;   float* qv_s = S + S_QV;
    float* qin_s = S + S_QIN; float* sb = S + S_SB;  float* ctx = S + S_CTX;
    float* rel = S + S_REL;  float* msk = S + S_MSK; int* kix = (int*)(S + S_KIX);
    float* qc = S + S_QC;    float* inv = S + S_INV;

    const float kw0 = sm[O_KPW + lane*3+0], kw1 = sm[O_KPW + lane*3+1],
                kw2 = sm[O_KPW + lane*3+2], kb = sm[O_KPB + lane];

    for (int q0 = blockIdx.x * NSLOT; q0 < m; q0 += gridDim.x * NSLOT) {
        const int q = q0 + slot;
        const bool valid = (q < m);

        if (valid) {
            if (lane < 3) qc[lane] = qcoord[q * 3 + lane];
            if (lane < K_) {
                const int idx = q * K_ + lane;
                kix[lane] = kidx[idx];
                float mv;
                if (mode == 0)      mv = ((const unsigned char*)kmask)[idx] ? 1.f : 0.f;
                else if (mode == 1) mv = ((const int*)kmask)[idx] ? 1.f : 0.f;
                else                mv = (((const float*)kmask)[idx] != 0.f) ? 1.f : 0.f;
                msk[lane] = mv;
            }
        }
        __syncthreads();

        if (valid) {   // relative coords + q_in
            const float c0 = qc[0], c1 = qc[1], c2 = qc[2];
            if (lane < K_) {
                const int vi = kix[lane];
                rel[lane*3+0] = vcoord[vi*3+0] - c0;
                rel[lane*3+1] = vcoord[vi*3+1] - c1;
                rel[lane*3+2] = vcoord[vi*3+2] - c2;
            }
            float t = sm[O_QPB + lane];
            t = fmaf(sm[O_QPW + lane*3+0], c0, t);
            t = fmaf(sm[O_QPW + lane*3+1], c1, t);
            t = fmaf(sm[O_QPW + lane*3+2], c2, t);
            qin_s[lane] = fmaxf(t, 0.f);
        }
        __syncthreads();

        if (valid) {   // q = (q_in @ wq^T + bq) * d^-0.5
            float acc = sm[O_BQ + lane];
            #pragma unroll
            for (int cp = 0; cp < 64; cp += 4) {
                float4 a = *(const float4*)&qin_s[cp];
                acc = fmaf(a.x, sm[O_WQT + (cp+0)*64 + lane], acc);
                acc = fmaf(a.y, sm[O_WQT + (cp+1)*64 + lane], acc);
                acc = fmaf(a.z, sm[O_WQT + (cp+2)*64 + lane], acc);
                acc = fmaf(a.w, sm[O_WQT + (cp+3)*64 + lane], acc);
            }
            qv_s[lane] = acc * 0.25f;
        }
        __syncthreads();

        if (valid) {   // u[h] = wk_h^T @ q_h ; gather k_in
            #pragma unroll
            for (int h = 0; h < 4; h++) {
                float acc = 0.f;
                #pragma unroll
                for (int j = 0; j < 16; j++)
                    acc = fmaf(sm[O_WK + (h*16+j)*64 + lane], qv_s[h*16+j], acc);
                u_s[h*64 + lane] = acc;
            }
            #pragma unroll 4
            for (int k = 0; k < K_; k++) {
                const float f = __ldg(&vf[kix[k] * 64 + lane]);
                float kp = kb;
                kp = fmaf(kw0, rel[k*3+0], kp);
                kp = fmaf(kw1, rel[k*3+1], kp);
                kp = fmaf(kw2, rel[k*3+2], kp);
                kin[k*KSTR + lane] = f + fmaxf(kp, 0.f);
            }
        }
        __syncthreads();

        if (valid) {   // scores
            #pragma unroll
            for (int r = 0; r < 3; r++) {
                const int si = lane + 64*r;
                const int h = si / 48, k = si - h*48;
                const float2* kr = (const float2*)&kin[k*KSTR];
                const float2* ur = (const float2*)&u_s[h*64];
                float acc = 0.f;
                #pragma unroll
                for (int c2 = 0; c2 < 32; c2++) {
                    float2 a = kr[c2], b = ur[c2];
                    acc = fmaf(a.x, b.x, acc); acc = fmaf(a.y, b.y, acc);
                }
                sb[k*4 + h] = (msk[k] != 0.f) ? -1e9f : acc;
            }
        }
        __syncthreads();

        if (valid) {   // softmax: 16 lanes per head
            const int h = lane >> 4, j = lane & 15;
            float v0 = sb[j*4+h], v1 = sb[(j+16)*4+h], v2 = sb[(j+32)*4+h];
            float mx = fmaxf(v0, fmaxf(v1, v2));
            #pragma unroll
            for (int off = 8; off; off >>= 1)
                mx = fmaxf(mx, __shfl_xor_sync(0xffffffffu, mx, off));
            float e0 = __expf(v0-mx), e1 = __expf(v1-mx), e2 = __expf(v2-mx);
            sb[j*4+h] = e0; sb[(j+16)*4+h] = e1; sb[(j+32)*4+h] = e2;
            float s = e0 + e1 + e2;
            #pragma unroll
            for (int off = 8; off; off >>= 1)
                s += __shfl_xor_sync(0xffffffffu, s, off);
            if (j == 0) inv[h] = 1.0f / s;
        }
        __syncthreads();

        if (valid) {   // ctx[h,c] = sum_k a[h,k] k_in[k,c]
            float a0=0.f, a1=0.f, a2=0.f, a3=0.f;
            #pragma unroll 8
            for (int k = 0; k < K_; k++) {
                float4 e = *(const float4*)&sb[k*4];
                float kv = kin[k*KSTR + lane];
                a0 = fmaf(e.x, kv, a0); a1 = fmaf(e.y, kv, a1);
                a2 = fmaf(e.z, kv, a2); a3 = fmaf(e.w, kv, a3);
            }
            ctx[0*65+lane] = a0*inv[0]; ctx[1*65+lane] = a1*inv[1];
            ctx[2*65+lane] = a2*inv[2]; ctx[3*65+lane] = a3*inv[3];
        }
        __syncthreads();

        if (valid) {   // o = ctx @ wv^T + bv
            const float* cr = ctx + (lane >> 4) * 65;
            float acc = sm[O_BV + lane];
            #pragma unroll 8
            for (int cp = 0; cp < 64; cp++)
                acc = fmaf(cr[cp], sm[O_WVT + cp*64 + lane], acc);
            g_obuf[q*64 + lane] = acc;
        }
        __syncthreads();
    }
}

// ============================================================================
// Kernel 2: out_proj + FFN + BN1 + output layer + BN2 + ReLU
// ============================================================================
__global__ __launch_bounds__(256, 1) void ffn_kernel(
    const float* __restrict__ opw, const float* __restrict__ opb,
    const float* __restrict__ w1,  const float* __restrict__ b1,
    const float* __restrict__ w2,  const float* __restrict__ b2,
    const float* __restrict__ ng,  const float* __restrict__ nb,
    const float* __restrict__ nm,  const float* __restrict__ nv,
    const float* __restrict__ ow,  const float* __restrict__ ob,
    const float* __restrict__ g2,  const float* __restrict__ b2n,
    const float* __restrict__ m2,  const float* __restrict__ v2,
    float* __restrict__ out, int m, long long out_size)
{
    extern __shared__ float sm[];
    const int tid = threadIdx.x;

    // zero any tail of d_out beyond m*64 (poison insurance)
    for (long long i = (long long)m * 64 + (long long)blockIdx.x * blockDim.x + tid;
         i < out_size; i += (long long)gridDim.x * blockDim.x)
        out[i] = 0.f;

    for (int i = tid; i < 4096; i += 256) {
        int c = i & 63, cp = i >> 6;
        sm[Q_WOT  + i] = opw[c*64 + cp];
        sm[Q_WOUT + i] = ow[c*64 + cp];
    }
    for (int i = tid; i < 16384; i += 256) {
        sm[Q_W1T + i] = w1[(i & 255)*64 + (i >> 8)];
        sm[Q_W2T + i] = w2[(i & 63)*256 + (i >> 6)];
    }
    if (tid < 64) {
        sm[Q_BO + tid] = opb[tid];
        sm[Q_B2 + tid] = b2[tid];
        sm[Q_OUTB + tid] = ob[tid];
        float s1 = ng[tid] * rsqrtf(nv[tid] + 1e-5f);
        sm[Q_BN1S + tid] = s1;
        sm[Q_BN1T + tid] = nb[tid] - nm[tid] * s1;
        float s2 = g2[tid] * rsqrtf(v2[tid] + 1e-5f);
        sm[Q_BN2S + tid] = s2;
        sm[Q_BN2T + tid] = b2n[tid] - m2[tid] * s2;
    }
    sm[Q_B1 + tid] = b1[tid];
    __syncthreads();

    const int c = tid & 63, g = tid >> 6;
    float* G = sm + Q_GRP + g * GRP_FL;
    float* o4 = G; float* att4 = G + 256; float* h4 = G + 512;

    for (int qb = blockIdx.x * 16; qb < m; qb += gridDim.x * 16) {
        const int qg = qb + g * 4;
        float4 ov;
        ov.x = (qg+0 < m) ? g_obuf[(qg+0)*64 + c] : 0.f;
        ov.y = (qg+1 < m) ? g_obuf[(qg+1)*64 + c] : 0.f;
        ov.z = (qg+2 < m) ? g_obuf[(qg+2)*64 + c] : 0.f;
        ov.w = (qg+3 < m) ? g_obuf[(qg+3)*64 + c] : 0.f;
        *(float4*)&o4[c*4] = ov;
        __syncthreads();

        const float bo_ = sm[Q_BO + c];
        float4 att = make_float4(bo_, bo_, bo_, bo_);
        #pragma unroll 8
        for (int cp = 0; cp < 64; cp++) {
            float w = sm[Q_WOT + cp*64 + c];
            float4 a = *(const float4*)&o4[cp*4];
            att.x = fmaf(a.x,w,att.x); att.y = fmaf(a.y,w,att.y);
            att.z = fmaf(a.z,w,att.z); att.w = fmaf(a.w,w,att.w);
        }
        *(float4*)&att4[c*4] = att;
        __syncthreads();

        float4 h[4];
        #pragma unroll
        for (int r = 0; r < 4; r++) {
            float bb = sm[Q_B1 + c + 64*r];
            h[r] = make_float4(bb, bb, bb, bb);
        }
        #pragma unroll 4
        for (int cp = 0; cp < 64; cp++) {
            float4 a = *(const float4*)&att4[cp*4];
            #pragma unroll
            for (int r = 0; r < 4; r++) {
                float w = sm[Q_W1T + cp*256 + c + 64*r];
                h[r].x = fmaf(a.x,w,h[r].x); h[r].y = fmaf(a.y,w,h[r].y);
                h[r].z = fmaf(a.z,w,h[r].z); h[r].w = fmaf(a.w,w,h[r].w);
            }
        }
        #pragma unroll
        for (int r = 0; r < 4; r++) {
            h[r].x = fmaxf(h[r].x,0.f); h[r].y = fmaxf(h[r].y,0.f);
            h[r].z = fmaxf(h[r].z,0.f); h[r].w = fmaxf(h[r].w,0.f);
            *(float4*)&h4[(c + 64*r)*4] = h[r];
        }
        __syncthreads();

        const float bb2 = sm[Q_B2 + c];
        float4 x = make_float4(att.x+bb2, att.y+bb2, att.z+bb2, att.w+bb2);
        #pragma unroll 8
        for (int f = 0; f < 256; f++) {
            float w = sm[Q_W2T + f*64 + c];
            float4 hv = *(const float4*)&h4[f*4];
            x.x = fmaf(hv.x,w,x.x); x.y = fmaf(hv.y,w,x.y);
            x.z = fmaf(hv.z,w,x.z); x.w = fmaf(hv.w,w,x.w);
        }
        const float s1 = sm[Q_BN1S + c], t1 = sm[Q_BN1T + c];
        x.x = fmaf(x.x,s1,t1); x.y = fmaf(x.y,s1,t1);
        x.z = fmaf(x.z,s1,t1); x.w = fmaf(x.w,s1,t1);
        __syncthreads();
        *(float4*)&o4[c*4] = x;
        __syncthreads();

        float4 y = make_float4(0.f,0.f,0.f,0.f);
        #pragma unroll 8
        for (int cp = 0; cp < 64; cp++) {
            float w = sm[Q_WOUT + cp*64 + c];
            float4 xv = *(const float4*)&o4[cp*4];
            y.x = fmaf(xv.x,w,y.x); y.y = fmaf(xv.y,w,y.y);
            y.z = fmaf(xv.z,w,y.z); y.w = fmaf(xv.w,w,y.w);
        }
        const float obc = sm[Q_OUTB + c], s2 = sm[Q_BN2S + c], t2 = sm[Q_BN2T + c];
        y.x = fmaxf(fmaf(y.x+obc, s2, t2), 0.f);
        y.y = fmaxf(fmaf(y.y+obc, s2, t2), 0.f);
        y.z = fmaxf(fmaf(y.z+obc, s2, t2), 0.f);
        y.w = fmaxf(fmaf(y.w+obc, s2, t2), 0.f);
        if (qg+0 < m) out[(qg+0)*64 + c] = y.x;
        if (qg+1 < m) out[(qg+1)*64 + c] = y.y;
        if (qg+2 < m) out[(qg+2)*64 + c] = y.z;
        if (qg+3 < m) out[(qg+3)*64 + c] = y.w;
        __syncthreads();
    }
}

extern "C" void kernel_launch(void* const* d_in, const int* in_sizes, int n_in,
                              void* d_out, int out_size)
{
    const float* vf  = (const float*)d_in[0];
    const float* vc  = (const float*)d_in[1];
    const float* qc  = (const float*)d_in[2];
    const int*   ki  = (const int*)d_in[3];
    const void*  km  = d_in[4];
    const float* qpw = (const float*)d_in[5];
    const float* qpb = (const float*)d_in[6];
    const float* kpw = (const float*)d_in[7];
    const float* kpb = (const float*)d_in[8];
    const float* ipw = (const float*)d_in[9];
    const float* ipb = (const float*)d_in[10];
    const float* opw = (const float*)d_in[11];
    const float* opb = (const float*)d_in[12];
    const float* w1  = (const float*)d_in[13];
    const float* b1  = (const float*)d_in[14];
    const float* w2  = (const float*)d_in[15];
    const float* b2  = (const float*)d_in[16];
    const float* ng  = (const float*)d_in[17];
    const float* nb  = (const float*)d_in[18];
    const float* nm  = (const float*)d_in[19];
    const float* nv  = (const float*)d_in[20];
    const float* ow  = (const float*)d_in[21];
    const float* ob  = (const float*)d_in[22];
    const float* g2  = (const float*)d_in[23];
    const float* b2n = (const float*)d_in[24];
    const float* m2  = (const float*)d_in[25];
    const float* v2  = (const float*)d_in[26];

    int m = in_sizes[2] / 3;
    if (m > MQ_MAX) m = MQ_MAX;

    cudaFuncSetAttribute(attn_kernel, cudaFuncAttributeMaxDynamicSharedMemorySize, SMEM1_BYTES);
    cudaFuncSetAttribute(ffn_kernel, cudaFuncAttributeMaxDynamicSharedMemorySize, SMEM2_BYTES);

    attn_kernel<<<148, 512, SMEM1_BYTES>>>(vf, vc, qc, ki, km, qpw, qpb, kpw, kpb, ipw, ipb, m);
    ffn_kernel<<<148, 256, SMEM2_BYTES>>>(opw, opb, w1, b1, w2, b2, ng, nb, nm, nv,
                                          ow, ob, g2, b2n, m2, v2, (float*)d_out, m,
                                          (long long)out_size);
}

// round 6
// speedup vs baseline: 1.1924x; 1.1924x over previous
#include <cuda_runtime.h>

constexpr int C_ = 64, K_ = 48, MQ_MAX = 25000, NSLOT = 8, KSTR = 66;

// kernel1 smem offsets (floats)
constexpr int O_WQT=0, O_WK=4096, O_WVT=8192, O_BQ=12288, O_BV=12352,
  O_QPW=12416, O_QPB=12608, O_KPW=12672, O_KPB=12864, O_SLOT=12928;
constexpr int S_KIN=0, S_U=3168, S_QV=3424, S_QIN=3488, S_SB=3552, S_CTX=3744,
  S_REL=4004, S_MSK=4148, S_KIX=4196, S_INV=4248, SLOT_FL=4256;
constexpr int SMEM1_BYTES = (O_SLOT + NSLOT*SLOT_FL) * 4;   // 187904

// kernel2 smem offsets (floats) — Q8 grouping
constexpr int Q_WOT=0, Q_W1T=4096, Q_W2T=20480, Q_WOUT=36864, Q_BO=40960,
  Q_B1=41024, Q_B2=41280, Q_BN1S=41344, Q_BN1T=41408, Q_BN2S=41472,
  Q_BN2T=41536, Q_OUTB=41600, Q_GRP=41664, GRP_FL=3072;  // o8(512)|att8(512)|h8(2048)
constexpr int SMEM2_BYTES = (Q_GRP + 4*GRP_FL) * 4;         // 215808

__device__ float g_obuf[MQ_MAX * C_];

// 64-thread named barrier (2 warps). ids 1..8; 0 is reserved for __syncthreads.
#define BAR64(id) asm volatile("bar.sync %0, 64;" :: "r"(id) : "memory")

// Block-local detection of key_mask storage: 0=uint8, 1=int32, 2=float32.
__device__ __forceinline__ int detect_mask_mode(const unsigned char* __restrict__ b,
                                                int* scratch, int tid, int nthr) {
    unsigned my123 = 0, my3f = 0;
    for (int i = tid * 8; i < tid * 8 + 8; i++) {
        if (i < 4096) {
            unsigned v = b[i];
            if ((i & 3) && v) my123 = 1;
            if ((i & 3) == 3 && v == 0x3fu) my3f = 1;
        }
    }
    unsigned w123 = __ballot_sync(0xffffffffu, my123 != 0);
    unsigned w3f  = __ballot_sync(0xffffffffu, my3f  != 0);
    int nw = nthr >> 5;
    if ((tid & 31) == 0) {
        scratch[(tid >> 5) * 2 + 0] = (w123 != 0);
        scratch[(tid >> 5) * 2 + 1] = (w3f  != 0);
    }
    __syncthreads();
    if (tid == 0) {
        int a123 = 0, a3f = 0;
        for (int w = 0; w < nw; w++) { a123 |= scratch[w*2]; a3f |= scratch[w*2+1]; }
        scratch[64] = (a123 == 0) ? 1 : (a3f ? 2 : 0);
    }
    __syncthreads();
    int mode = scratch[64];
    __syncthreads();
    return mode;
}

// ============================================================================
// Kernel 1: gather + pos-proj + restructured MHA -> g_obuf
// 8 independent slots of 64 threads; per-slot named barriers only.
// ============================================================================
__global__ __launch_bounds__(512, 1) void attn_kernel(
    const float* __restrict__ vf, const float* __restrict__ vcoord,
    const float* __restrict__ qcoord, const int* __restrict__ kidx,
    const void* __restrict__ kmask,
    const float* __restrict__ qpw_g, const float* __restrict__ qpb_g,
    const float* __restrict__ kpw_g, const float* __restrict__ kpb_g,
    const float* __restrict__ ipW, const float* __restrict__ ipB, int m)
{
    extern __shared__ float sm[];
    const int tid = threadIdx.x;

    for (int i = tid; i < 4096; i += 512) {
        int c = i & 63, cp = i >> 6;
        sm[O_WQT + i] = ipW[c * 64 + cp];           // wq^T
        sm[O_WK  + i] = ipW[4096 + i];              // wk row-major
        sm[O_WVT + i] = ipW[(128 + c) * 64 + cp];   // wv^T
    }
    if (tid < 64) {
        sm[O_BQ + tid] = ipB[tid];
        sm[O_BV + tid] = ipB[128 + tid];
        sm[O_QPB + tid] = qpb_g[tid];
        sm[O_KPB + tid] = kpb_g[tid];
    }
    if (tid < 192) { sm[O_QPW + tid] = qpw_g[tid]; sm[O_KPW + tid] = kpw_g[tid]; }
    __syncthreads();

    const int mode = detect_mask_mode((const unsigned char*)kmask,
                                      (int*)(sm + O_SLOT), tid, 512);

    const int slot = tid >> 6, lane = tid & 63;
    const int bid = slot + 1;
    float* S = sm + O_SLOT + slot * SLOT_FL;
    float* kin = S + S_KIN;  float* u_s = S + S_U;   float* qv_s = S + S_QV;
    float* qin_s = S + S_QIN; float* sb = S + S_SB;  float* ctx = S + S_CTX;
    float* rel = S + S_REL;  float* msk = S + S_MSK; int* kix = (int*)(S + S_KIX);
    float* inv = S + S_INV;

    const float kw0 = sm[O_KPW + lane*3+0], kw1 = sm[O_KPW + lane*3+1],
                kw2 = sm[O_KPW + lane*3+2], kb = sm[O_KPB + lane];

    for (int q0 = blockIdx.x * NSLOT; q0 < m; q0 += gridDim.x * NSLOT) {
        const int q = q0 + slot;
        const bool valid = (q < m);

        if (valid) {   // P01: qcoords (lane-private), key idx/mask/rel (own lane), q_in
            const float c0 = __ldg(&qcoord[q*3+0]);
            const float c1 = __ldg(&qcoord[q*3+1]);
            const float c2 = __ldg(&qcoord[q*3+2]);
            if (lane < K_) {
                const int idx = q * K_ + lane;
                const int vi = __ldg(&kidx[idx]);
                kix[lane] = vi;
                float mv;
                if (mode == 0)      mv = ((const unsigned char*)kmask)[idx] ? 1.f : 0.f;
                else if (mode == 1) mv = ((const int*)kmask)[idx] ? 1.f : 0.f;
                else                mv = (((const float*)kmask)[idx] != 0.f) ? 1.f : 0.f;
                msk[lane] = mv;
                rel[lane*3+0] = __ldg(&vcoord[vi*3+0]) - c0;
                rel[lane*3+1] = __ldg(&vcoord[vi*3+1]) - c1;
                rel[lane*3+2] = __ldg(&vcoord[vi*3+2]) - c2;
            }
            float t = sm[O_QPB + lane];
            t = fmaf(sm[O_QPW + lane*3+0], c0, t);
            t = fmaf(sm[O_QPW + lane*3+1], c1, t);
            t = fmaf(sm[O_QPW + lane*3+2], c2, t);
            qin_s[lane] = fmaxf(t, 0.f);
        }
        BAR64(bid);

        if (valid) {   // P2: q = (q_in @ wq^T + bq) * d^-0.5
            float acc = sm[O_BQ + lane];
            #pragma unroll
            for (int cp = 0; cp < 64; cp += 4) {
                float4 a = *(const float4*)&qin_s[cp];
                acc = fmaf(a.x, sm[O_WQT + (cp+0)*64 + lane], acc);
                acc = fmaf(a.y, sm[O_WQT + (cp+1)*64 + lane], acc);
                acc = fmaf(a.z, sm[O_WQT + (cp+2)*64 + lane], acc);
                acc = fmaf(a.w, sm[O_WQT + (cp+3)*64 + lane], acc);
            }
            qv_s[lane] = acc * 0.25f;
        }
        BAR64(bid);

        if (valid) {   // P3: u[h] = wk_h^T @ q_h ; gather k_in (channel = lane)
            #pragma unroll
            for (int h = 0; h < 4; h++) {
                float acc = 0.f;
                #pragma unroll
                for (int j = 0; j < 16; j++)
                    acc = fmaf(sm[O_WK + (h*16+j)*64 + lane], qv_s[h*16+j], acc);
                u_s[h*64 + lane] = acc;
            }
            #pragma unroll 4
            for (int k = 0; k < K_; k++) {
                const float f = __ldg(&vf[kix[k] * 64 + lane]);
                float kp = kb;
                kp = fmaf(kw0, rel[k*3+0], kp);
                kp = fmaf(kw1, rel[k*3+1], kp);
                kp = fmaf(kw2, rel[k*3+2], kp);
                kin[k*KSTR + lane] = f + fmaxf(kp, 0.f);
            }
        }
        BAR64(bid);

        if (valid && lane < K_) {   // P4: scores — lane = key, all 4 heads
            const int k = lane;
            const float2* kr = (const float2*)&kin[k*KSTR];
            const float2* u0 = (const float2*)&u_s[0];
            const float2* u1 = (const float2*)&u_s[64];
            const float2* u2 = (const float2*)&u_s[128];
            const float2* u3 = (const float2*)&u_s[192];
            float4 acc = make_float4(0.f, 0.f, 0.f, 0.f);
            #pragma unroll 8
            for (int c2 = 0; c2 < 32; c2++) {
                float2 kv = kr[c2];
                float2 a0 = u0[c2], a1 = u1[c2], a2 = u2[c2], a3 = u3[c2];
                acc.x = fmaf(kv.x, a0.x, acc.x); acc.x = fmaf(kv.y, a0.y, acc.x);
                acc.y = fmaf(kv.x, a1.x, acc.y); acc.y = fmaf(kv.y, a1.y, acc.y);
                acc.z = fmaf(kv.x, a2.x, acc.z); acc.z = fmaf(kv.y, a2.y, acc.z);
                acc.w = fmaf(kv.x, a3.x, acc.w); acc.w = fmaf(kv.y, a3.y, acc.w);
            }
            if (msk[k] != 0.f) acc = make_float4(-1e9f, -1e9f, -1e9f, -1e9f);
            *(float4*)&sb[k*4] = acc;
        }
        BAR64(bid);

        if (valid) {   // P5: softmax over k per head (16 lanes per head)
            const int h = lane >> 4, j = lane & 15;
            float v0 = sb[j*4+h], v1 = sb[(j+16)*4+h], v2 = sb[(j+32)*4+h];
            float mx = fmaxf(v0, fmaxf(v1, v2));
            #pragma unroll
            for (int off = 8; off; off >>= 1)
                mx = fmaxf(mx, __shfl_xor_sync(0xffffffffu, mx, off));
            float e0 = __expf(v0-mx), e1 = __expf(v1-mx), e2 = __expf(v2-mx);
            sb[j*4+h] = e0; sb[(j+16)*4+h] = e1; sb[(j+32)*4+h] = e2;
            float s = e0 + e1 + e2;
            #pragma unroll
            for (int off = 8; off; off >>= 1)
                s += __shfl_xor_sync(0xffffffffu, s, off);
            if (j == 0) inv[h] = 1.0f / s;
        }
        BAR64(bid);

        if (valid) {   // P6: ctx[h,c] = sum_k a[h,k] k_in[k,c]
            float a0=0.f, a1=0.f, a2=0.f, a3=0.f;
            #pragma unroll 8
            for (int k = 0; k < K_; k++) {
                float4 e = *(const float4*)&sb[k*4];
                float kv = kin[k*KSTR + lane];
                a0 = fmaf(e.x, kv, a0); a1 = fmaf(e.y, kv, a1);
                a2 = fmaf(e.z, kv, a2); a3 = fmaf(e.w, kv, a3);
            }
            ctx[0*65+lane] = a0*inv[0]; ctx[1*65+lane] = a1*inv[1];
            ctx[2*65+lane] = a2*inv[2]; ctx[3*65+lane] = a3*inv[3];
        }
        BAR64(bid);

        if (valid) {   // P7: o = ctx @ wv^T + bv -> global (no trailing barrier needed)
            const float* cr = ctx + (lane >> 4) * 65;
            float acc = sm[O_BV + lane];
            #pragma unroll 8
            for (int cp = 0; cp < 64; cp++)
                acc = fmaf(cr[cp], sm[O_WVT + cp*64 + lane], acc);
            g_obuf[q*64 + lane] = acc;
        }
        // ctx(n) reads vs ctx(n+1) writes are separated by >=5 named barriers.
    }
}

// ============================================================================
// Kernel 2: out_proj + FFN + BN1 + output layer + BN2 + ReLU
// 4 independent groups of 64 threads, 8 queries per group per tile.
// ============================================================================
__global__ __launch_bounds__(256, 1) void ffn_kernel(
    const float* __restrict__ opw, const float* __restrict__ opb,
    const float* __restrict__ w1,  const float* __restrict__ b1,
    const float* __restrict__ w2,  const float* __restrict__ b2,
    const float* __restrict__ ng,  const float* __restrict__ nb,
    const float* __restrict__ nm,  const float* __restrict__ nv,
    const float* __restrict__ ow,  const float* __restrict__ ob,
    const float* __restrict__ g2,  const float* __restrict__ b2n,
    const float* __restrict__ m2,  const float* __restrict__ v2,
    float* __restrict__ out, int m, long long out_size)
{
    extern __shared__ float sm[];
    const int tid = threadIdx.x;

    // zero any tail of d_out beyond m*64 (poison insurance)
    for (long long i = (long long)m * 64 + (long long)blockIdx.x * blockDim.x + tid;
         i < out_size; i += (long long)gridDim.x * blockDim.x)
        out[i] = 0.f;

    for (int i = tid; i < 4096; i += 256) {
        int c = i & 63, cp = i >> 6;
        sm[Q_WOT  + i] = opw[c*64 + cp];
        sm[Q_WOUT + i] = ow[c*64 + cp];
    }
    for (int i = tid; i < 16384; i += 256) {
        sm[Q_W1T + i] = w1[(i & 255)*64 + (i >> 8)];
        sm[Q_W2T + i] = w2[(i & 63)*256 + (i >> 6)];
    }
    if (tid < 64) {
        sm[Q_BO + tid] = opb[tid];
        sm[Q_B2 + tid] = b2[tid];
        sm[Q_OUTB + tid] = ob[tid];
        float s1 = ng[tid] * rsqrtf(nv[tid] + 1e-5f);
        sm[Q_BN1S + tid] = s1;
        sm[Q_BN1T + tid] = nb[tid] - nm[tid] * s1;
        float s2 = g2[tid] * rsqrtf(v2[tid] + 1e-5f);
        sm[Q_BN2S + tid] = s2;
        sm[Q_BN2T + tid] = b2n[tid] - m2[tid] * s2;
    }
    sm[Q_B1 + tid] = b1[tid];
    __syncthreads();

    const int c = tid & 63, g = tid >> 6;
    const int bid = g + 1;
    float* G = sm + Q_GRP + g * GRP_FL;
    float* o8 = G; float* att8 = G + 512; float* h8 = G + 1024;

    const float bo_ = sm[Q_BO + c];
    const float bb2 = sm[Q_B2 + c];
    const float s1 = sm[Q_BN1S + c], t1 = sm[Q_BN1T + c];
    const float obc = sm[Q_OUTB + c], s2 = sm[Q_BN2S + c], t2 = sm[Q_BN2T + c];

    for (int qb = blockIdx.x * 32; qb < m; qb += gridDim.x * 32) {
        const int qg = qb + g * 8;
        float ov[8];
        #pragma unroll
        for (int j = 0; j < 8; j++)
            ov[j] = (qg + j < m) ? g_obuf[(qg+j)*64 + c] : 0.f;
        *(float4*)&o8[c*8]   = make_float4(ov[0], ov[1], ov[2], ov[3]);
        *(float4*)&o8[c*8+4] = make_float4(ov[4], ov[5], ov[6], ov[7]);
        BAR64(bid);

        // attend = o @ Wo^T + bo
        float att[8];
        #pragma unroll
        for (int j = 0; j < 8; j++) att[j] = bo_;
        #pragma unroll 4
        for (int cp = 0; cp < 64; cp++) {
            float w = sm[Q_WOT + cp*64 + c];
            float4 a0 = *(const float4*)&o8[cp*8];
            float4 a1 = *(const float4*)&o8[cp*8+4];
            att[0] = fmaf(a0.x,w,att[0]); att[1] = fmaf(a0.y,w,att[1]);
            att[2] = fmaf(a0.z,w,att[2]); att[3] = fmaf(a0.w,w,att[3]);
            att[4] = fmaf(a1.x,w,att[4]); att[5] = fmaf(a1.y,w,att[5]);
            att[6] = fmaf(a1.z,w,att[6]); att[7] = fmaf(a1.w,w,att[7]);
        }
        *(float4*)&att8[c*8]   = make_float4(att[0], att[1], att[2], att[3]);
        *(float4*)&att8[c*8+4] = make_float4(att[4], att[5], att[6], att[7]);
        BAR64(bid);

        // hidden = relu(attend @ W1^T + b1): 4 f-rows x 8 queries per thread
        float h[4][8];
        #pragma unroll
        for (int r = 0; r < 4; r++) {
            float bb = sm[Q_B1 + c + 64*r];
            #pragma unroll
            for (int j = 0; j < 8; j++) h[r][j] = bb;
        }
        #pragma unroll 2
        for (int cp = 0; cp < 64; cp++) {
            float4 a0 = *(const float4*)&att8[cp*8];
            float4 a1 = *(const float4*)&att8[cp*8+4];
            #pragma unroll
            for (int r = 0; r < 4; r++) {
                float w = sm[Q_W1T + cp*256 + c + 64*r];
                h[r][0] = fmaf(a0.x,w,h[r][0]); h[r][1] = fmaf(a0.y,w,h[r][1]);
                h[r][2] = fmaf(a0.z,w,h[r][2]); h[r][3] = fmaf(a0.w,w,h[r][3]);
                h[r][4] = fmaf(a1.x,w,h[r][4]); h[r][5] = fmaf(a1.y,w,h[r][5]);
                h[r][6] = fmaf(a1.z,w,h[r][6]); h[r][7] = fmaf(a1.w,w,h[r][7]);
            }
        }
        #pragma unroll
        for (int r = 0; r < 4; r++) {
            #pragma unroll
            for (int j = 0; j < 8; j++) h[r][j] = fmaxf(h[r][j], 0.f);
            *(float4*)&h8[(c+64*r)*8]   = make_float4(h[r][0], h[r][1], h[r][2], h[r][3]);
            *(float4*)&h8[(c+64*r)*8+4] = make_float4(h[r][4], h[r][5], h[r][6], h[r][7]);
        }
        BAR64(bid);

        // x = attend + hidden @ W2^T + b2, then BN1
        float x[8];
        #pragma unroll
        for (int j = 0; j < 8; j++) x[j] = att[j] + bb2;
        #pragma unroll 4
        for (int f = 0; f < 256; f++) {
            float w = sm[Q_W2T + f*64 + c];
            float4 h0 = *(const float4*)&h8[f*8];
            float4 h1 = *(const float4*)&h8[f*8+4];
            x[0] = fmaf(h0.x,w,x[0]); x[1] = fmaf(h0.y,w,x[1]);
            x[2] = fmaf(h0.z,w,x[2]); x[3] = fmaf(h0.w,w,x[3]);
            x[4] = fmaf(h1.x,w,x[4]); x[5] = fmaf(h1.y,w,x[5]);
            x[6] = fmaf(h1.z,w,x[6]); x[7] = fmaf(h1.w,w,x[7]);
        }
        #pragma unroll
        for (int j = 0; j < 8; j++) x[j] = fmaf(x[j], s1, t1);
        *(float4*)&o8[c*8]   = make_float4(x[0], x[1], x[2], x[3]);   // reuse o8
        *(float4*)&o8[c*8+4] = make_float4(x[4], x[5], x[6], x[7]);
        BAR64(bid);

        // y = relu(BN2(x @ Wout^T + ob))
        float y[8];
        #pragma unroll
        for (int j = 0; j < 8; j++) y[j] = 0.f;
        #pragma unroll 4
        for (int cp = 0; cp < 64; cp++) {
            float w = sm[Q_WOUT + cp*64 + c];
            float4 x0 = *(const float4*)&o8[cp*8];
            float4 x1 = *(const float4*)&o8[cp*8+4];
            y[0] = fmaf(x0.x,w,y[0]); y[1] = fmaf(x0.y,w,y[1]);
            y[2] = fmaf(x0.z,w,y[2]); y[3] = fmaf(x0.w,w,y[3]);
            y[4] = fmaf(x1.x,w,y[4]); y[5] = fmaf(x1.y,w,y[5]);
            y[6] = fmaf(x1.z,w,y[6]); y[7] = fmaf(x1.w,w,y[7]);
        }
        #pragma unroll
        for (int j = 0; j < 8; j++) {
            float v = fmaxf(fmaf(y[j] + obc, s2, t2), 0.f);
            if (qg + j < m) out[(qg+j)*64 + c] = v;
        }
        BAR64(bid);   // protect o8 before next tile's writes
    }
}

extern "C" void kernel_launch(void* const* d_in, const int* in_sizes, int n_in,
                              void* d_out, int out_size)
{
    const float* vf  = (const float*)d_in[0];
    const float* vc  = (const float*)d_in[1];
    const float* qc  = (const float*)d_in[2];
    const int*   ki  = (const int*)d_in[3];
    const void*  km  = d_in[4];
    const float* qpw = (const float*)d_in[5];
    const float* qpb = (const float*)d_in[6];
    const float* kpw = (const float*)d_in[7];
    const float* kpb = (const float*)d_in[8];
    const float* ipw = (const float*)d_in[9];
    const float* ipb = (const float*)d_in[10];
    const float* opw = (const float*)d_in[11];
    const float* opb = (const float*)d_in[12];
    const float* w1  = (const float*)d_in[13];
    const float* b1  = (const float*)d_in[14];
    const float* w2  = (const float*)d_in[15];
    const float* b2  = (const float*)d_in[16];
    const float* ng  = (const float*)d_in[17];
    const float* nb  = (const float*)d_in[18];
    const float* nm  = (const float*)d_in[19];
    const float* nv  = (const float*)d_in[20];
    const float* ow  = (const float*)d_in[21];
    const float* ob  = (const float*)d_in[22];
    const float* g2  = (const float*)d_in[23];
    const float* b2n = (const float*)d_in[24];
    const float* m2  = (const float*)d_in[25];
    const float* v2  = (const float*)d_in[26];

    int m = in_sizes[2] / 3;
    if (m > MQ_MAX) m = MQ_MAX;

    cudaFuncSetAttribute(attn_kernel, cudaFuncAttributeMaxDynamicSharedMemorySize, SMEM1_BYTES);
    cudaFuncSetAttribute(ffn_kernel, cudaFuncAttributeMaxDynamicSharedMemorySize, SMEM2_BYTES);

    attn_kernel<<<148, 512, SMEM1_BYTES>>>(vf, vc, qc, ki, km, qpw, qpb, kpw, kpb, ipw, ipb, m);
    ffn_kernel<<<148, 256, SMEM2_BYTES>>>(opw, opb, w1, b1, w2, b2, ng, nb, nm, nv,
                                          ow, ob, g2, b2n, m2, v2, (float*)d_out, m,
                                          (long long)out_size);
}

// round 8
// speedup vs baseline: 1.6324x; 1.3690x over previous
#include <cuda_runtime.h>

constexpr int C_ = 64, K_ = 48, MQ_MAX = 25000, NSLOT = 8, KSTR = 66;

// kernel1 smem offsets (floats) — KSTR=66: 264B rows, float2-aligned
constexpr int O_WQT=0, O_WK=4096, O_WVT=8192, O_BQ=12288, O_BV=12352,
  O_QPW=12416, O_QPB=12608, O_KPW=12672, O_KPB=12864, O_SLOT=12928;
constexpr int S_KIN=0, S_U=3168, S_QV=3424, S_QIN=3488, S_SB=3552, S_CTX=3744,
  S_REL=4004, S_MSK=4148, S_KIX=4196, S_INV=4248, SLOT_FL=4256;
constexpr int SMEM1_BYTES = (O_SLOT + NSLOT*SLOT_FL) * 4;   // 187904

// kernel2 smem offsets (floats) — 8 groups x Q4
constexpr int Q_WOT=0, Q_W1T=4096, Q_W2T=20480, Q_WOUT=36864, Q_BO=40960,
  Q_B1=41024, Q_B2=41280, Q_BN1S=41344, Q_BN1T=41408, Q_BN2S=41472,
  Q_BN2T=41536, Q_OUTB=41600, Q_GRP=41664, GRP_FL=1536;  // o4(256)|att4(256)|h4(1024)
constexpr int SMEM2_BYTES = (Q_GRP + 8*GRP_FL) * 4;         // 215808

__device__ float g_obuf[MQ_MAX * C_];

// 64-thread named barrier (2 warps). ids 1..8; 0 reserved for __syncthreads.
#define BAR64(id) asm volatile("bar.sync %0, 64;" :: "r"(id) : "memory")

// Block-local detection of key_mask storage: 0=uint8, 1=int32, 2=float32.
__device__ __forceinline__ int detect_mask_mode(const unsigned char* __restrict__ b,
                                                int* scratch, int tid, int nthr) {
    unsigned my123 = 0, my3f = 0;
    for (int i = tid * 8; i < tid * 8 + 8; i++) {
        if (i < 4096) {
            unsigned v = b[i];
            if ((i & 3) && v) my123 = 1;
            if ((i & 3) == 3 && v == 0x3fu) my3f = 1;
        }
    }
    unsigned w123 = __ballot_sync(0xffffffffu, my123 != 0);
    unsigned w3f  = __ballot_sync(0xffffffffu, my3f  != 0);
    int nw = nthr >> 5;
    if ((tid & 31) == 0) {
        scratch[(tid >> 5) * 2 + 0] = (w123 != 0);
        scratch[(tid >> 5) * 2 + 1] = (w3f  != 0);
    }
    __syncthreads();
    if (tid == 0) {
        int a123 = 0, a3f = 0;
        for (int w = 0; w < nw; w++) { a123 |= scratch[w*2]; a3f |= scratch[w*2+1]; }
        scratch[64] = (a123 == 0) ? 1 : (a3f ? 2 : 0);
    }
    __syncthreads();
    int mode = scratch[64];
    __syncthreads();
    return mode;
}

// ============================================================================
// Kernel 1: gather + pos-proj + restructured MHA -> g_obuf
// 8 independent slots of 64 threads; per-slot named barriers only.
// ============================================================================
__global__ __launch_bounds__(512, 1) void attn_kernel(
    const float* __restrict__ vf, const float* __restrict__ vcoord,
    const float* __restrict__ qcoord, const int* __restrict__ kidx,
    const void* __restrict__ kmask,
    const float* __restrict__ qpw_g, const float* __restrict__ qpb_g,
    const float* __restrict__ kpw_g, const float* __restrict__ kpb_g,
    const float* __restrict__ ipW, const float* __restrict__ ipB, int m)
{
    extern __shared__ float sm[];
    const int tid = threadIdx.x;

    for (int i = tid; i < 4096; i += 512) {
        int c = i & 63, cp = i >> 6;
        sm[O_WQT + i] = ipW[c * 64 + cp];           // wq^T
        sm[O_WK  + i] = ipW[4096 + i];              // wk row-major
        sm[O_WVT + i] = ipW[(128 + c) * 64 + cp];   // wv^T
    }
    if (tid < 64) {
        sm[O_BQ + tid] = ipB[tid];
        sm[O_BV + tid] = ipB[128 + tid];
        sm[O_QPB + tid] = qpb_g[tid];
        sm[O_KPB + tid] = kpb_g[tid];
    }
    if (tid < 192) { sm[O_QPW + tid] = qpw_g[tid]; sm[O_KPW + tid] = kpw_g[tid]; }
    __syncthreads();

    const int mode = detect_mask_mode((const unsigned char*)kmask,
                                      (int*)(sm + O_SLOT), tid, 512);

    const int slot = tid >> 6, lane = tid & 63;
    const int bid = slot + 1;
    float* S = sm + O_SLOT + slot * SLOT_FL;
    float* kin = S + S_KIN;  float* u_s = S + S_U;   float* qv_s = S + S_QV;
    float* qin_s = S + S_QIN; float* sb = S + S_SB;  float* ctx = S + S_CTX;
    float* rel = S + S_REL;  float* msk = S + S_MSK; int* kix = (int*)(S + S_KIX);
    float* inv = S + S_INV;

    const float kw0 = sm[O_KPW + lane*3+0], kw1 = sm[O_KPW + lane*3+1],
                kw2 = sm[O_KPW + lane*3+2], kb_ = sm[O_KPB + lane];

    for (int q0 = blockIdx.x * NSLOT; q0 < m; q0 += gridDim.x * NSLOT) {
        const int q = q0 + slot;
        const bool valid = (q < m);

        if (valid) {   // P01: key idx/mask/rel (own lane), q_in
            const float c0 = __ldg(&qcoord[q*3+0]);
            const float c1 = __ldg(&qcoord[q*3+1]);
            const float c2 = __ldg(&qcoord[q*3+2]);
            if (lane < K_) {
                const int idx = q * K_ + lane;
                const int vi = __ldg(&kidx[idx]);
                kix[lane] = vi;
                float mv;
                if (mode == 0)      mv = ((const unsigned char*)kmask)[idx] ? 1.f : 0.f;
                else if (mode == 1) mv = ((const int*)kmask)[idx] ? 1.f : 0.f;
                else                mv = (((const float*)kmask)[idx] != 0.f) ? 1.f : 0.f;
                msk[lane] = mv;
                rel[lane*3+0] = __ldg(&vcoord[vi*3+0]) - c0;
                rel[lane*3+1] = __ldg(&vcoord[vi*3+1]) - c1;
                rel[lane*3+2] = __ldg(&vcoord[vi*3+2]) - c2;
            }
            float t = sm[O_QPB + lane];
            t = fmaf(sm[O_QPW + lane*3+0], c0, t);
            t = fmaf(sm[O_QPW + lane*3+1], c1, t);
            t = fmaf(sm[O_QPW + lane*3+2], c2, t);
            qin_s[lane] = fmaxf(t, 0.f);
        }
        BAR64(bid);

        if (valid) {   // P2: q = (q_in @ wq^T + bq) * d^-0.5
            float acc = sm[O_BQ + lane];
            #pragma unroll
            for (int cp = 0; cp < 64; cp += 4) {
                float4 a = *(const float4*)&qin_s[cp];
                acc = fmaf(a.x, sm[O_WQT + (cp+0)*64 + lane], acc);
                acc = fmaf(a.y, sm[O_WQT + (cp+1)*64 + lane], acc);
                acc = fmaf(a.z, sm[O_WQT + (cp+2)*64 + lane], acc);
                acc = fmaf(a.w, sm[O_WQT + (cp+3)*64 + lane], acc);
            }
            qv_s[lane] = acc * 0.25f;
        }
        BAR64(bid);

        if (valid) {   // P3: u[h] = wk_h^T @ q_h ; gather k_in (batched LDG, MLP=16)
            #pragma unroll
            for (int h = 0; h < 4; h++) {
                float acc = 0.f;
                #pragma unroll
                for (int j = 0; j < 16; j++)
                    acc = fmaf(sm[O_WK + (h*16+j)*64 + lane], qv_s[h*16+j], acc);
                u_s[h*64 + lane] = acc;
            }
            #pragma unroll
            for (int kb = 0; kb < K_; kb += 16) {
                float fv[16];
                #pragma unroll
                for (int j = 0; j < 16; j++)
                    fv[j] = __ldg(&vf[kix[kb+j] * 64 + lane]);
                #pragma unroll
                for (int j = 0; j < 16; j++) {
                    const int k = kb + j;
                    float kp = kb_;
                    kp = fmaf(kw0, rel[k*3+0], kp);
                    kp = fmaf(kw1, rel[k*3+1], kp);
                    kp = fmaf(kw2, rel[k*3+2], kp);
                    kin[k*KSTR + lane] = fv[j] + fmaxf(kp, 0.f);
                }
            }
        }
        BAR64(bid);

        if (valid && lane < K_) {   // P4: scores — lane = key, all 4 heads
            const int k = lane;
            const float2* kr = (const float2*)&kin[k*KSTR];
            const float2* u0 = (const float2*)&u_s[0];
            const float2* u1 = (const float2*)&u_s[64];
            const float2* u2 = (const float2*)&u_s[128];
            const float2* u3 = (const float2*)&u_s[192];
            float4 acc = make_float4(0.f, 0.f, 0.f, 0.f);
            #pragma unroll 8
            for (int c2 = 0; c2 < 32; c2++) {
                float2 kv = kr[c2];
                float2 a0 = u0[c2], a1 = u1[c2], a2 = u2[c2], a3 = u3[c2];
                acc.x = fmaf(kv.x, a0.x, acc.x); acc.x = fmaf(kv.y, a0.y, acc.x);
                acc.y = fmaf(kv.x, a1.x, acc.y); acc.y = fmaf(kv.y, a1.y, acc.y);
                acc.z = fmaf(kv.x, a2.x, acc.z); acc.z = fmaf(kv.y, a2.y, acc.z);
                acc.w = fmaf(kv.x, a3.x, acc.w); acc.w = fmaf(kv.y, a3.y, acc.w);
            }
            if (msk[k] != 0.f) acc = make_float4(-1e9f, -1e9f, -1e9f, -1e9f);
            *(float4*)&sb[k*4] = acc;
        }
        BAR64(bid);

        if (valid) {   // P5: softmax over k per head (16 lanes per head)
            const int h = lane >> 4, j = lane & 15;
            float v0 = sb[j*4+h], v1 = sb[(j+16)*4+h], v2 = sb[(j+32)*4+h];
            float mx = fmaxf(v0, fmaxf(v1, v2));
            #pragma unroll
            for (int off = 8; off; off >>= 1)
                mx = fmaxf(mx, __shfl_xor_sync(0xffffffffu, mx, off));
            float e0 = __expf(v0-mx), e1 = __expf(v1-mx), e2 = __expf(v2-mx);
            sb[j*4+h] = e0; sb[(j+16)*4+h] = e1; sb[(j+32)*4+h] = e2;
            float s = e0 + e1 + e2;
            #pragma unroll
            for (int off = 8; off; off >>= 1)
                s += __shfl_xor_sync(0xffffffffu, s, off);
            if (j == 0) inv[h] = 1.0f / s;
        }
        BAR64(bid);

        if (valid) {   // P6: ctx[h,c] = sum_k a[h,k] k_in[k,c]
            float a0=0.f, a1=0.f, a2=0.f, a3=0.f;
            #pragma unroll 8
            for (int k = 0; k < K_; k++) {
                float4 e = *(const float4*)&sb[k*4];
                float kv = kin[k*KSTR + lane];
                a0 = fmaf(e.x, kv, a0); a1 = fmaf(e.y, kv, a1);
                a2 = fmaf(e.z, kv, a2); a3 = fmaf(e.w, kv, a3);
            }
            ctx[0*65+lane] = a0*inv[0]; ctx[1*65+lane] = a1*inv[1];
            ctx[2*65+lane] = a2*inv[2]; ctx[3*65+lane] = a3*inv[3];
        }
        BAR64(bid);

        if (valid) {   // P7: o = ctx @ wv^T + bv -> global
            const float* cr = ctx + (lane >> 4) * 65;
            float acc = sm[O_BV + lane];
            #pragma unroll 8
            for (int cp = 0; cp < 64; cp++)
                acc = fmaf(cr[cp], sm[O_WVT + cp*64 + lane], acc);
            g_obuf[q*64 + lane] = acc;
        }
        // ctx(n) reads vs next-iteration writes separated by >=5 named barriers.
    }
}

// ============================================================================
// Kernel 2: out_proj + FFN + BN1 + output layer + BN2 + ReLU
// 512 threads: 8 independent groups of 64 threads, 4 queries per group.
// ============================================================================
__global__ __launch_bounds__(512, 1) void ffn_kernel(
    const float* __restrict__ opw, const float* __restrict__ opb,
    const float* __restrict__ w1,  const float* __restrict__ b1,
    const float* __restrict__ w2,  const float* __restrict__ b2,
    const float* __restrict__ ng,  const float* __restrict__ nb,
    const float* __restrict__ nm,  const float* __restrict__ nv,
    const float* __restrict__ ow,  const float* __restrict__ ob,
    const float* __restrict__ g2,  const float* __restrict__ b2n,
    const float* __restrict__ m2,  const float* __restrict__ v2,
    float* __restrict__ out, int m, long long out_size)
{
    extern __shared__ float sm[];
    const int tid = threadIdx.x;

    // zero any tail of d_out beyond m*64 (poison insurance)
    for (long long i = (long long)m * 64 + (long long)blockIdx.x * blockDim.x + tid;
         i < out_size; i += (long long)gridDim.x * blockDim.x)
        out[i] = 0.f;

    for (int i = tid; i < 4096; i += 512) {
        int c = i & 63, cp = i >> 6;
        sm[Q_WOT  + i] = opw[c*64 + cp];
        sm[Q_WOUT + i] = ow[c*64 + cp];
    }
    for (int i = tid; i < 16384; i += 512) {
        sm[Q_W1T + i] = w1[(i & 255)*64 + (i >> 8)];
        sm[Q_W2T + i] = w2[(i & 63)*256 + (i >> 6)];
    }
    if (tid < 64) {
        sm[Q_BO + tid] = opb[tid];
        sm[Q_B2 + tid] = b2[tid];
        sm[Q_OUTB + tid] = ob[tid];
        float s1 = ng[tid] * rsqrtf(nv[tid] + 1e-5f);
        sm[Q_BN1S + tid] = s1;
        sm[Q_BN1T + tid] = nb[tid] - nm[tid] * s1;
        float s2 = g2[tid] * rsqrtf(v2[tid] + 1e-5f);
        sm[Q_BN2S + tid] = s2;
        sm[Q_BN2T + tid] = b2n[tid] - m2[tid] * s2;
    }
    if (tid < 256) sm[Q_B1 + tid] = b1[tid];
    __syncthreads();

    const int c = tid & 63, g = tid >> 6;
    const int bid = g + 1;
    float* G = sm + Q_GRP + g * GRP_FL;
    float* o4 = G; float* att4 = G + 256; float* h4 = G + 512;

    const float bo_ = sm[Q_BO + c];
    const float bb2 = sm[Q_B2 + c];
    const float s1 = sm[Q_BN1S + c], t1 = sm[Q_BN1T + c];
    const float obc = sm[Q_OUTB + c], s2 = sm[Q_BN2S + c], t2 = sm[Q_BN2T + c];

    for (int qb = blockIdx.x * 32; qb < m; qb += gridDim.x * 32) {
        const int qg = qb + g * 4;
        float4 ov;
        ov.x = (qg+0 < m) ? g_obuf[(qg+0)*64 + c] : 0.f;
        ov.y = (qg+1 < m) ? g_obuf[(qg+1)*64 + c] : 0.f;
        ov.z = (qg+2 < m) ? g_obuf[(qg+2)*64 + c] : 0.f;
        ov.w = (qg+3 < m) ? g_obuf[(qg+3)*64 + c] : 0.f;
        *(float4*)&o4[c*4] = ov;
        BAR64(bid);

        // attend = o @ Wo^T + bo
        float4 att = make_float4(bo_, bo_, bo_, bo_);
        #pragma unroll 8
        for (int cp = 0; cp < 64; cp++) {
            float w = sm[Q_WOT + cp*64 + c];
            float4 a = *(const float4*)&o4[cp*4];
            att.x = fmaf(a.x,w,att.x); att.y = fmaf(a.y,w,att.y);
            att.z = fmaf(a.z,w,att.z); att.w = fmaf(a.w,w,att.w);
        }
        *(float4*)&att4[c*4] = att;
        BAR64(bid);

        // hidden = relu(attend @ W1^T + b1): 4 f-rows per thread
        float4 h[4];
        #pragma unroll
        for (int r = 0; r < 4; r++) {
            float bb = sm[Q_B1 + c + 64*r];
            h[r] = make_float4(bb, bb, bb, bb);
        }
        #pragma unroll 4
        for (int cp = 0; cp < 64; cp++) {
            float4 a = *(const float4*)&att4[cp*4];
            #pragma unroll
            for (int r = 0; r < 4; r++) {
                float w = sm[Q_W1T + cp*256 + c + 64*r];
                h[r].x = fmaf(a.x,w,h[r].x); h[r].y = fmaf(a.y,w,h[r].y);
                h[r].z = fmaf(a.z,w,h[r].z); h[r].w = fmaf(a.w,w,h[r].w);
            }
        }
        #pragma unroll
        for (int r = 0; r < 4; r++) {
            h[r].x = fmaxf(h[r].x,0.f); h[r].y = fmaxf(h[r].y,0.f);
            h[r].z = fmaxf(h[r].z,0.f); h[r].w = fmaxf(h[r].w,0.f);
            *(float4*)&h4[(c + 64*r)*4] = h[r];
        }
        BAR64(bid);

        // x = attend + hidden @ W2^T + b2, then BN1
        float4 x = make_float4(att.x+bb2, att.y+bb2, att.z+bb2, att.w+bb2);
        #pragma unroll 8
        for (int f = 0; f < 256; f++) {
            float w = sm[Q_W2T + f*64 + c];
            float4 hv = *(const float4*)&h4[f*4];
            x.x = fmaf(hv.x,w,x.x); x.y = fmaf(hv.y,w,x.y);
            x.z = fmaf(hv.z,w,x.z); x.w = fmaf(hv.w,w,x.w);
        }
        x.x = fmaf(x.x,s1,t1); x.y = fmaf(x.y,s1,t1);
        x.z = fmaf(x.z,s1,t1); x.w = fmaf(x.w,s1,t1);
        BAR64(bid);
        *(float4*)&o4[c*4] = x;     // reuse o4 as x4
        BAR64(bid);

        // y = relu(BN2(x @ Wout^T + ob))
        float4 y = make_float4(0.f,0.f,0.f,0.f);
        #pragma unroll 8
        for (int cp = 0; cp < 64; cp++) {
            float w = sm[Q_WOUT + cp*64 + c];
            float4 xv = *(const float4*)&o4[cp*4];
            y.x = fmaf(xv.x,w,y.x); y.y = fmaf(xv.y,w,y.y);
            y.z = fmaf(xv.z,w,y.z); y.w = fmaf(xv.w,w,y.w);
        }
        y.x = fmaxf(fmaf(y.x+obc, s2, t2), 0.f);
        y.y = fmaxf(fmaf(y.y+obc, s2, t2), 0.f);
        y.z = fmaxf(fmaf(y.z+obc, s2, t2), 0.f);
        y.w = fmaxf(fmaf(y.w+obc, s2, t2), 0.f);
        if (qg+0 < m) out[(qg+0)*64 + c] = y.x;
        if (qg+1 < m) out[(qg+1)*64 + c] = y.y;
        if (qg+2 < m) out[(qg+2)*64 + c] = y.z;
        if (qg+3 < m) out[(qg+3)*64 + c] = y.w;
        BAR64(bid);   // protect o4 before next tile's writes
    }
}

extern "C" void kernel_launch(void* const* d_in, const int* in_sizes, int n_in,
                              void* d_out, int out_size)
{
    const float* vf  = (const float*)d_in[0];
    const float* vc  = (const float*)d_in[1];
    const float* qc  = (const float*)d_in[2];
    const int*   ki  = (const int*)d_in[3];
    const void*  km  = d_in[4];
    const float* qpw = (const float*)d_in[5];
    const float* qpb = (const float*)d_in[6];
    const float* kpw = (const float*)d_in[7];
    const float* kpb = (const float*)d_in[8];
    const float* ipw = (const float*)d_in[9];
    const float* ipb = (const float*)d_in[10];
    const float* opw = (const float*)d_in[11];
    const float* opb = (const float*)d_in[12];
    const float* w1  = (const float*)d_in[13];
    const float* b1  = (const float*)d_in[14];
    const float* w2  = (const float*)d_in[15];
    const float* b2  = (const float*)d_in[16];
    const float* ng  = (const float*)d_in[17];
    const float* nb  = (const float*)d_in[18];
    const float* nm  = (const float*)d_in[19];
    const float* nv  = (const float*)d_in[20];
    const float* ow  = (const float*)d_in[21];
    const float* ob  = (const float*)d_in[22];
    const float* g2  = (const float*)d_in[23];
    const float* b2n = (const float*)d_in[24];
    const float* m2  = (const float*)d_in[25];
    const float* v2  = (const float*)d_in[26];

    int m = in_sizes[2] / 3;
    if (m > MQ_MAX) m = MQ_MAX;

    cudaFuncSetAttribute(attn_kernel, cudaFuncAttributeMaxDynamicSharedMemorySize, SMEM1_BYTES);
    cudaFuncSetAttribute(ffn_kernel, cudaFuncAttributeMaxDynamicSharedMemorySize, SMEM2_BYTES);

    attn_kernel<<<148, 512, SMEM1_BYTES>>>(vf, vc, qc, ki, km, qpw, qpb, kpw, kpb, ipw, ipb, m);
    ffn_kernel<<<148, 512, SMEM2_BYTES>>>(opw, opb, w1, b1, w2, b2, ng, nb, nm, nv,
                                          ow, ob, g2, b2n, m2, v2, (float*)d_out, m,
                                          (long long)out_size);
}

// round 9
// speedup vs baseline: 1.7083x; 1.0465x over previous
#include <cuda_runtime.h>

constexpr int C_ = 64, K_ = 48, MQ_MAX = 25000, NSLOT = 8, KSTR = 66, CTXSTR = 68;

// kernel1 smem offsets (floats)
constexpr int O_WQT=0, O_WK=4096, O_WVT=8192, O_BQ=12288, O_BV=12352,
  O_QPW=12416, O_QPB=12608, O_KPW=12672, O_KPB=12864, O_SLOT=12928;
constexpr int S_KIN=0, S_U=3168, S_QV=3424, S_QIN=3488, S_SB=3552, S_CTX=3744,
  S_REL4=4016, S_MSK=4208, S_INV=4256, SLOT_FL=4264;
constexpr int SMEM1_BYTES = (O_SLOT + NSLOT*SLOT_FL) * 4;   // 188160

// kernel2 smem offsets (floats) — 8 groups x Q4
constexpr int Q_WOT=0, Q_W1T=4096, Q_W2T=20480, Q_WOUT=36864, Q_BO=40960,
  Q_B1=41024, Q_B2=41280, Q_BN1S=41344, Q_BN1T=41408, Q_BN2S=41472,
  Q_BN2T=41536, Q_OUTB=41600, Q_GRP=41664, GRP_FL=1536;
constexpr int SMEM2_BYTES = (Q_GRP + 8*GRP_FL) * 4;         // 215808

__device__ float g_obuf[MQ_MAX * C_];

#define BAR64(id) asm volatile("bar.sync %0, 64;" :: "r"(id) : "memory")

// Block-local detection of key_mask storage: 0=uint8, 1=int32, 2=float32.
__device__ __forceinline__ int detect_mask_mode(const unsigned char* __restrict__ b,
                                                int* scratch, int tid, int nthr) {
    unsigned my123 = 0, my3f = 0;
    for (int i = tid * 8; i < tid * 8 + 8; i++) {
        if (i < 4096) {
            unsigned v = b[i];
            if ((i & 3) && v) my123 = 1;
            if ((i & 3) == 3 && v == 0x3fu) my3f = 1;
        }
    }
    unsigned w123 = __ballot_sync(0xffffffffu, my123 != 0);
    unsigned w3f  = __ballot_sync(0xffffffffu, my3f  != 0);
    int nw = nthr >> 5;
    if ((tid & 31) == 0) {
        scratch[(tid >> 5) * 2 + 0] = (w123 != 0);
        scratch[(tid >> 5) * 2 + 1] = (w3f  != 0);
    }
    __syncthreads();
    if (tid == 0) {
        int a123 = 0, a3f = 0;
        for (int w = 0; w < nw; w++) { a123 |= scratch[w*2]; a3f |= scratch[w*2+1]; }
        scratch[64] = (a123 == 0) ? 1 : (a3f ? 2 : 0);
    }
    __syncthreads();
    int mode = scratch[64];
    __syncthreads();
    return mode;
}

// ============================================================================
// Kernel 1: gather + pos-proj + restructured MHA -> g_obuf
// ============================================================================
__global__ __launch_bounds__(512, 1) void attn_kernel(
    const float* __restrict__ vf, const float* __restrict__ vcoord,
    const float* __restrict__ qcoord, const int* __restrict__ kidx,
    const void* __restrict__ kmask,
    const float* __restrict__ qpw_g, const float* __restrict__ qpb_g,
    const float* __restrict__ kpw_g, const float* __restrict__ kpb_g,
    const float* __restrict__ ipW, const float* __restrict__ ipB, int m)
{
    extern __shared__ float sm[];
    const int tid = threadIdx.x;

    for (int i = tid; i < 4096; i += 512) {
        int c = i & 63, cp = i >> 6;
        sm[O_WQT + i] = ipW[c * 64 + cp];           // wq^T
        sm[O_WK  + i] = ipW[4096 + i];              // wk row-major
        sm[O_WVT + i] = ipW[(128 + c) * 64 + cp];   // wv^T
    }
    if (tid < 64) {
        sm[O_BQ + tid] = ipB[tid];
        sm[O_BV + tid] = ipB[128 + tid];
        sm[O_QPB + tid] = qpb_g[tid];
        sm[O_KPB + tid] = kpb_g[tid];
    }
    if (tid < 192) { sm[O_QPW + tid] = qpw_g[tid]; sm[O_KPW + tid] = kpw_g[tid]; }
    __syncthreads();

    const int mode = detect_mask_mode((const unsigned char*)kmask,
                                      (int*)(sm + O_SLOT), tid, 512);

    const int slot = tid >> 6, lane = tid & 63;
    const int bid = slot + 1;
    float* S = sm + O_SLOT + slot * SLOT_FL;
    float* kin = S + S_KIN;  float* u_s = S + S_U;   float* qv_s = S + S_QV;
    float* qin_s = S + S_QIN; float* sb = S + S_SB;  float* ctx = S + S_CTX;
    float4* rel4 = (float4*)(S + S_REL4);
    float* msk = S + S_MSK;  float* inv = S + S_INV;

    const float kw0 = sm[O_KPW + lane*3+0], kw1 = sm[O_KPW + lane*3+1],
                kw2 = sm[O_KPW + lane*3+2], kb_ = sm[O_KPB + lane];

    for (int q0 = blockIdx.x * NSLOT; q0 < m; q0 += gridDim.x * NSLOT) {
        const int q = q0 + slot;
        const bool valid = (q < m);

        if (valid) {   // P01: key idx/mask/rel4 (own lane), q_in
            const float c0 = __ldg(&qcoord[q*3+0]);
            const float c1 = __ldg(&qcoord[q*3+1]);
            const float c2 = __ldg(&qcoord[q*3+2]);
            if (lane < K_) {
                const int idx = q * K_ + lane;
                const int vi = __ldg(&kidx[idx]);
                float mv;
                if (mode == 0)      mv = ((const unsigned char*)kmask)[idx] ? 1.f : 0.f;
                else if (mode == 1) mv = ((const int*)kmask)[idx] ? 1.f : 0.f;
                else                mv = (((const float*)kmask)[idx] != 0.f) ? 1.f : 0.f;
                msk[lane] = mv;
                float4 r;
                r.x = __ldg(&vcoord[vi*3+0]) - c0;
                r.y = __ldg(&vcoord[vi*3+1]) - c1;
                r.z = __ldg(&vcoord[vi*3+2]) - c2;
                r.w = __int_as_float(vi);
                rel4[lane] = r;
            }
            float t = sm[O_QPB + lane];
            t = fmaf(sm[O_QPW + lane*3+0], c0, t);
            t = fmaf(sm[O_QPW + lane*3+1], c1, t);
            t = fmaf(sm[O_QPW + lane*3+2], c2, t);
            qin_s[lane] = fmaxf(t, 0.f);
        }
        BAR64(bid);

        if (valid) {   // P2: q = (q_in @ wq^T + bq) * d^-0.5
            float acc = sm[O_BQ + lane];
            #pragma unroll
            for (int cp = 0; cp < 64; cp += 4) {
                float4 a = *(const float4*)&qin_s[cp];
                acc = fmaf(a.x, sm[O_WQT + (cp+0)*64 + lane], acc);
                acc = fmaf(a.y, sm[O_WQT + (cp+1)*64 + lane], acc);
                acc = fmaf(a.z, sm[O_WQT + (cp+2)*64 + lane], acc);
                acc = fmaf(a.w, sm[O_WQT + (cp+3)*64 + lane], acc);
            }
            qv_s[lane] = acc * 0.25f;
        }
        BAR64(bid);

        if (valid) {   // P3: u[h] = wk_h^T @ q_h ; gather k_in (batched LDG)
            #pragma unroll
            for (int h = 0; h < 4; h++) {
                float acc = 0.f;
                #pragma unroll
                for (int j4 = 0; j4 < 4; j4++) {
                    float4 qv = *(const float4*)&qv_s[h*16 + j4*4];
                    acc = fmaf(sm[O_WK + (h*16+j4*4+0)*64 + lane], qv.x, acc);
                    acc = fmaf(sm[O_WK + (h*16+j4*4+1)*64 + lane], qv.y, acc);
                    acc = fmaf(sm[O_WK + (h*16+j4*4+2)*64 + lane], qv.z, acc);
                    acc = fmaf(sm[O_WK + (h*16+j4*4+3)*64 + lane], qv.w, acc);
                }
                u_s[h*64 + lane] = acc;
            }
            #pragma unroll
            for (int kb = 0; kb < K_; kb += 16) {
                float4 r4[16];
                #pragma unroll
                for (int j = 0; j < 16; j++) r4[j] = rel4[kb+j];
                float fv[16];
                #pragma unroll
                for (int j = 0; j < 16; j++)
                    fv[j] = __ldg(&vf[__float_as_int(r4[j].w) * 64 + lane]);
                #pragma unroll
                for (int j = 0; j < 16; j++) {
                    float kp = kb_;
                    kp = fmaf(kw0, r4[j].x, kp);
                    kp = fmaf(kw1, r4[j].y, kp);
                    kp = fmaf(kw2, r4[j].z, kp);
                    kin[(kb+j)*KSTR + lane] = fv[j] + fmaxf(kp, 0.f);
                }
            }
        }
        BAR64(bid);

        if (valid && lane < K_) {   // P4: scores — lane = key, all 4 heads
            const int k = lane;
            const float2* kr = (const float2*)&kin[k*KSTR];
            const float4* u4 = (const float4*)u_s;   // [h*16 + c4]
            float4 acc = make_float4(0.f, 0.f, 0.f, 0.f);
            #pragma unroll 4
            for (int c4 = 0; c4 < 16; c4++) {
                float2 ka = kr[2*c4], kc = kr[2*c4+1];
                float4 a0 = u4[c4], a1 = u4[16+c4], a2 = u4[32+c4], a3 = u4[48+c4];
                acc.x = fmaf(ka.x,a0.x, fmaf(ka.y,a0.y, fmaf(kc.x,a0.z, fmaf(kc.y,a0.w, acc.x))));
                acc.y = fmaf(ka.x,a1.x, fmaf(ka.y,a1.y, fmaf(kc.x,a1.z, fmaf(kc.y,a1.w, acc.y))));
                acc.z = fmaf(ka.x,a2.x, fmaf(ka.y,a2.y, fmaf(kc.x,a2.z, fmaf(kc.y,a2.w, acc.z))));
                acc.w = fmaf(ka.x,a3.x, fmaf(ka.y,a3.y, fmaf(kc.x,a3.z, fmaf(kc.y,a3.w, acc.w))));
            }
            if (msk[k] != 0.f) acc = make_float4(-1e9f, -1e9f, -1e9f, -1e9f);
            *(float4*)&sb[k*4] = acc;
        }
        BAR64(bid);

        if (valid) {   // P5: softmax over k per head (16 lanes per head)
            const int h = lane >> 4, j = lane & 15;
            float v0 = sb[j*4+h], v1 = sb[(j+16)*4+h], v2 = sb[(j+32)*4+h];
            float mx = fmaxf(v0, fmaxf(v1, v2));
            #pragma unroll
            for (int off = 8; off; off >>= 1)
                mx = fmaxf(mx, __shfl_xor_sync(0xffffffffu, mx, off));
            float e0 = __expf(v0-mx), e1 = __expf(v1-mx), e2 = __expf(v2-mx);
            sb[j*4+h] = e0; sb[(j+16)*4+h] = e1; sb[(j+32)*4+h] = e2;
            float s = e0 + e1 + e2;
            #pragma unroll
            for (int off = 8; off; off >>= 1)
                s += __shfl_xor_sync(0xffffffffu, s, off);
            if (j == 0) inv[h] = 1.0f / s;
        }
        BAR64(bid);

        if (valid) {   // P6: ctx[h,c] = sum_k a[h,k] k_in[k,c]
            float a0=0.f, a1=0.f, a2=0.f, a3=0.f;
            #pragma unroll 8
            for (int k = 0; k < K_; k++) {
                float4 e = *(const float4*)&sb[k*4];
                float kv = kin[k*KSTR + lane];
                a0 = fmaf(e.x, kv, a0); a1 = fmaf(e.y, kv, a1);
                a2 = fmaf(e.z, kv, a2); a3 = fmaf(e.w, kv, a3);
            }
            ctx[0*CTXSTR+lane] = a0*inv[0]; ctx[1*CTXSTR+lane] = a1*inv[1];
            ctx[2*CTXSTR+lane] = a2*inv[2]; ctx[3*CTXSTR+lane] = a3*inv[3];
        }
        BAR64(bid);

        if (valid) {   // P7: o = ctx @ wv^T + bv -> global (float4 ctx reads)
            const float4* cr4 = (const float4*)(ctx + (lane >> 4) * CTXSTR);
            float acc = sm[O_BV + lane];
            #pragma unroll 4
            for (int c4 = 0; c4 < 16; c4++) {
                float4 cv = cr4[c4];
                acc = fmaf(cv.x, sm[O_WVT + (c4*4+0)*64 + lane], acc);
                acc = fmaf(cv.y, sm[O_WVT + (c4*4+1)*64 + lane], acc);
                acc = fmaf(cv.z, sm[O_WVT + (c4*4+2)*64 + lane], acc);
                acc = fmaf(cv.w, sm[O_WVT + (c4*4+3)*64 + lane], acc);
            }
            g_obuf[q*64 + lane] = acc;
        }
    }
}

// ============================================================================
// Kernel 2: out_proj + FFN + BN1 + output layer + BN2 + ReLU
// 512 threads: 8 independent groups of 64 threads, 4 queries per group.
// ============================================================================
__global__ __launch_bounds__(512, 1) void ffn_kernel(
    const float* __restrict__ opw, const float* __restrict__ opb,
    const float* __restrict__ w1,  const float* __restrict__ b1,
    const float* __restrict__ w2,  const float* __restrict__ b2,
    const float* __restrict__ ng,  const float* __restrict__ nb,
    const float* __restrict__ nm,  const float* __restrict__ nv,
    const float* __restrict__ ow,  const float* __restrict__ ob,
    const float* __restrict__ g2,  const float* __restrict__ b2n,
    const float* __restrict__ m2,  const float* __restrict__ v2,
    float* __restrict__ out, int m, long long out_size)
{
    extern __shared__ float sm[];
    const int tid = threadIdx.x;

    for (long long i = (long long)m * 64 + (long long)blockIdx.x * blockDim.x + tid;
         i < out_size; i += (long long)gridDim.x * blockDim.x)
        out[i] = 0.f;

    for (int i = tid; i < 4096; i += 512) {
        int c = i & 63, cp = i >> 6;
        sm[Q_WOT  + i] = opw[c*64 + cp];
        sm[Q_WOUT + i] = ow[c*64 + cp];
    }
    for (int i = tid; i < 16384; i += 512) {
        sm[Q_W1T + i] = w1[(i & 255)*64 + (i >> 8)];
        sm[Q_W2T + i] = w2[(i & 63)*256 + (i >> 6)];
    }
    if (tid < 64) {
        sm[Q_BO + tid] = opb[tid];
        sm[Q_B2 + tid] = b2[tid];
        sm[Q_OUTB + tid] = ob[tid];
        float s1 = ng[tid] * rsqrtf(nv[tid] + 1e-5f);
        sm[Q_BN1S + tid] = s1;
        sm[Q_BN1T + tid] = nb[tid] - nm[tid] * s1;
        float s2 = g2[tid] * rsqrtf(v2[tid] + 1e-5f);
        sm[Q_BN2S + tid] = s2;
        sm[Q_BN2T + tid] = b2n[tid] - m2[tid] * s2;
    }
    if (tid < 256) sm[Q_B1 + tid] = b1[tid];
    __syncthreads();

    const int c = tid & 63, g = tid >> 6;
    const int bid = g + 1;
    float* G = sm + Q_GRP + g * GRP_FL;
    float* o4 = G; float* att4 = G + 256; float* h4 = G + 512;

    const float bo_ = sm[Q_BO + c];
    const float bb2 = sm[Q_B2 + c];
    const float s1 = sm[Q_BN1S + c], t1 = sm[Q_BN1T + c];
    const float obc = sm[Q_OUTB + c], s2 = sm[Q_BN2S + c], t2 = sm[Q_BN2T + c];

    for (int qb = blockIdx.x * 32; qb < m; qb += gridDim.x * 32) {
        const int qg = qb + g * 4;
        float4 ov;
        ov.x = (qg+0 < m) ? g_obuf[(qg+0)*64 + c] : 0.f;
        ov.y = (qg+1 < m) ? g_obuf[(qg+1)*64 + c] : 0.f;
        ov.z = (qg+2 < m) ? g_obuf[(qg+2)*64 + c] : 0.f;
        ov.w = (qg+3 < m) ? g_obuf[(qg+3)*64 + c] : 0.f;
        *(float4*)&o4[c*4] = ov;
        BAR64(bid);

        // attend = o @ Wo^T + bo
        float4 att = make_float4(bo_, bo_, bo_, bo_);
        #pragma unroll 8
        for (int cp = 0; cp < 64; cp++) {
            float w = sm[Q_WOT + cp*64 + c];
            float4 a = *(const float4*)&o4[cp*4];
            att.x = fmaf(a.x,w,att.x); att.y = fmaf(a.y,w,att.y);
            att.z = fmaf(a.z,w,att.z); att.w = fmaf(a.w,w,att.w);
        }
        *(float4*)&att4[c*4] = att;
        BAR64(bid);

        // hidden = relu(attend @ W1^T + b1)
        float4 h[4];
        #pragma unroll
        for (int r = 0; r < 4; r++) {
            float bb = sm[Q_B1 + c + 64*r];
            h[r] = make_float4(bb, bb, bb, bb);
        }
        #pragma unroll 4
        for (int cp = 0; cp < 64; cp++) {
            float4 a = *(const float4*)&att4[cp*4];
            #pragma unroll
            for (int r = 0; r < 4; r++) {
                float w = sm[Q_W1T + cp*256 + c + 64*r];
                h[r].x = fmaf(a.x,w,h[r].x); h[r].y = fmaf(a.y,w,h[r].y);
                h[r].z = fmaf(a.z,w,h[r].z); h[r].w = fmaf(a.w,w,h[r].w);
            }
        }
        #pragma unroll
        for (int r = 0; r < 4; r++) {
            h[r].x = fmaxf(h[r].x,0.f); h[r].y = fmaxf(h[r].y,0.f);
            h[r].z = fmaxf(h[r].z,0.f); h[r].w = fmaxf(h[r].w,0.f);
            *(float4*)&h4[(c + 64*r)*4] = h[r];
        }
        BAR64(bid);

        // x = attend + hidden @ W2^T + b2, then BN1
        float4 x = make_float4(att.x+bb2, att.y+bb2, att.z+bb2, att.w+bb2);
        #pragma unroll 8
        for (int f = 0; f < 256; f++) {
            float w = sm[Q_W2T + f*64 + c];
            float4 hv = *(const float4*)&h4[f*4];
            x.x = fmaf(hv.x,w,x.x); x.y = fmaf(hv.y,w,x.y);
            x.z = fmaf(hv.z,w,x.z); x.w = fmaf(hv.w,w,x.w);
        }
        x.x = fmaf(x.x,s1,t1); x.y = fmaf(x.y,s1,t1);
        x.z = fmaf(x.z,s1,t1); x.w = fmaf(x.w,s1,t1);
        *(float4*)&o4[c*4] = x;     // o4 readers (Wo loop) drained at att4 barrier
        BAR64(bid);

        // y = relu(BN2(x @ Wout^T + ob))
        float4 y = make_float4(0.f,0.f,0.f,0.f);
        #pragma unroll 8
        for (int cp = 0; cp < 64; cp++) {
            float w = sm[Q_WOUT + cp*64 + c];
            float4 xv = *(const float4*)&o4[cp*4];
            y.x = fmaf(xv.x,w,y.x); y.y = fmaf(xv.y,w,y.y);
            y.z = fmaf(xv.z,w,y.z); y.w = fmaf(xv.w,w,y.w);
        }
        y.x = fmaxf(fmaf(y.x+obc, s2, t2), 0.f);
        y.y = fmaxf(fmaf(y.y+obc, s2, t2), 0.f);
        y.z = fmaxf(fmaf(y.z+obc, s2, t2), 0.f);
        y.w = fmaxf(fmaf(y.w+obc, s2, t2), 0.f);
        if (qg+0 < m) out[(qg+0)*64 + c] = y.x;
        if (qg+1 < m) out[(qg+1)*64 + c] = y.y;
        if (qg+2 < m) out[(qg+2)*64 + c] = y.z;
        if (qg+3 < m) out[(qg+3)*64 + c] = y.w;
        BAR64(bid);   // protect o4 before next tile's writes
    }
}

extern "C" void kernel_launch(void* const* d_in, const int* in_sizes, int n_in,
                              void* d_out, int out_size)
{
    const float* vf  = (const float*)d_in[0];
    const float* vc  = (const float*)d_in[1];
    const float* qc  = (const float*)d_in[2];
    const int*   ki  = (const int*)d_in[3];
    const void*  km  = d_in[4];
    const float* qpw = (const float*)d_in[5];
    const float* qpb = (const float*)d_in[6];
    const float* kpw = (const float*)d_in[7];
    const float* kpb = (const float*)d_in[8];
    const float* ipw = (const float*)d_in[9];
    const float* ipb = (const float*)d_in[10];
    const float* opw = (const float*)d_in[11];
    const float* opb = (const float*)d_in[12];
    const float* w1  = (const float*)d_in[13];
    const float* b1  = (const float*)d_in[14];
    const float* w2  = (const float*)d_in[15];
    const float* b2  = (const float*)d_in[16];
    const float* ng  = (const float*)d_in[17];
    const float* nb  = (const float*)d_in[18];
    const float* nm  = (const float*)d_in[19];
    const float* nv  = (const float*)d_in[20];
    const float* ow  = (const float*)d_in[21];
    const float* ob  = (const float*)d_in[22];
    const float* g2  = (const float*)d_in[23];
    const float* b2n = (const float*)d_in[24];
    const float* m2  = (const float*)d_in[25];
    const float* v2  = (const float*)d_in[26];

    int m = in_sizes[2] / 3;
    if (m > MQ_MAX) m = MQ_MAX;

    cudaFuncSetAttribute(attn_kernel, cudaFuncAttributeMaxDynamicSharedMemorySize, SMEM1_BYTES);
    cudaFuncSetAttribute(ffn_kernel, cudaFuncAttributeMaxDynamicSharedMemorySize, SMEM2_BYTES);

    attn_kernel<<<148, 512, SMEM1_BYTES>>>(vf, vc, qc, ki, km, qpw, qpb, kpw, kpb, ipw, ipb, m);
    ffn_kernel<<<148, 512, SMEM2_BYTES>>>(opw, opb, w1, b1, w2, b2, ng, nb, nm, nv,
                                          ow, ob, g2, b2n, m2, v2, (float*)d_out, m,
                                          (long long)out_size);
}

// round 10
// speedup vs baseline: 1.7198x; 1.0067x over previous
#include <cuda_runtime.h>

constexpr int C_ = 64, K_ = 48, MQ_MAX = 25000, NSLOT = 8, KSTR = 66, CTXSTR = 68;

// kernel1 smem offsets (floats)
constexpr int O_WQT=0, O_WK=4096, O_WVT=8192, O_BQ=12288, O_BV=12352,
  O_QPW=12416, O_QPB=12608, O_KPW=12672, O_KPB=12864, O_SLOT=12928;
constexpr int S_KIN=0, S_U=3168, S_QV=3424, S_QIN=3488, S_SB=3552, S_CTX=3744,
  S_REL4=4016, S_MSK=4208, S_INV=4256, SLOT_FL=4264;
constexpr int SMEM1_BYTES = (O_SLOT + NSLOT*SLOT_FL) * 4;   // 188160

// kernel2 smem offsets (floats) — 4 groups x 128 threads, Q8
constexpr int Q_WOT=0, Q_W1T=4096, Q_W2T=20480, Q_WOUT=36864, Q_BO=40960,
  Q_B1=41024, Q_B2=41280, Q_BN1S=41344, Q_BN1T=41408, Q_BN2S=41472,
  Q_BN2T=41536, Q_OUTB=41600, Q_GRP=41664, GRP_FL=3072; // o8/xp(512)|att8(512)|h8/xs(2048)
constexpr int SMEM2_BYTES = (Q_GRP + 4*GRP_FL) * 4;         // 215808

__device__ float g_obuf[MQ_MAX * C_];

#define BAR64(id)  asm volatile("bar.sync %0, 64;"  :: "r"(id) : "memory")
#define BAR128(id) asm volatile("bar.sync %0, 128;" :: "r"(id) : "memory")

// Block-local detection of key_mask storage: 0=uint8, 1=int32, 2=float32.
__device__ __forceinline__ int detect_mask_mode(const unsigned char* __restrict__ b,
                                                int* scratch, int tid, int nthr) {
    unsigned my123 = 0, my3f = 0;
    for (int i = tid * 8; i < tid * 8 + 8; i++) {
        if (i < 4096) {
            unsigned v = b[i];
            if ((i & 3) && v) my123 = 1;
            if ((i & 3) == 3 && v == 0x3fu) my3f = 1;
        }
    }
    unsigned w123 = __ballot_sync(0xffffffffu, my123 != 0);
    unsigned w3f  = __ballot_sync(0xffffffffu, my3f  != 0);
    int nw = nthr >> 5;
    if ((tid & 31) == 0) {
        scratch[(tid >> 5) * 2 + 0] = (w123 != 0);
        scratch[(tid >> 5) * 2 + 1] = (w3f  != 0);
    }
    __syncthreads();
    if (tid == 0) {
        int a123 = 0, a3f = 0;
        for (int w = 0; w < nw; w++) { a123 |= scratch[w*2]; a3f |= scratch[w*2+1]; }
        scratch[64] = (a123 == 0) ? 1 : (a3f ? 2 : 0);
    }
    __syncthreads();
    int mode = scratch[64];
    __syncthreads();
    return mode;
}

// ============================================================================
// Kernel 1: gather + pos-proj + restructured MHA -> g_obuf
// 8 slots x 64 lanes; P01 global loads software-pipelined one query ahead.
// ============================================================================
__global__ __launch_bounds__(512, 1) void attn_kernel(
    const float* __restrict__ vf, const float* __restrict__ vcoord,
    const float* __restrict__ qcoord, const int* __restrict__ kidx,
    const void* __restrict__ kmask,
    const float* __restrict__ qpw_g, const float* __restrict__ qpb_g,
    const float* __restrict__ kpw_g, const float* __restrict__ kpb_g,
    const float* __restrict__ ipW, const float* __restrict__ ipB, int m)
{
    extern __shared__ float sm[];
    const int tid = threadIdx.x;

    for (int i = tid; i < 4096; i += 512) {
        int c = i & 63, cp = i >> 6;
        sm[O_WQT + i] = ipW[c * 64 + cp];           // wq^T
        sm[O_WK  + i] = ipW[4096 + i];              // wk row-major
        sm[O_WVT + i] = ipW[(128 + c) * 64 + cp];   // wv^T
    }
    if (tid < 64) {
        sm[O_BQ + tid] = ipB[tid];
        sm[O_BV + tid] = ipB[128 + tid];
        sm[O_QPB + tid] = qpb_g[tid];
        sm[O_KPB + tid] = kpb_g[tid];
    }
    if (tid < 192) { sm[O_QPW + tid] = qpw_g[tid]; sm[O_KPW + tid] = kpw_g[tid]; }
    __syncthreads();

    const int mode = detect_mask_mode((const unsigned char*)kmask,
                                      (int*)(sm + O_SLOT), tid, 512);

    const int slot = tid >> 6, lane = tid & 63;
    const int bid = slot + 1;
    float* S = sm + O_SLOT + slot * SLOT_FL;
    float* kin = S + S_KIN;  float* u_s = S + S_U;   float* qv_s = S + S_QV;
    float* qin_s = S + S_QIN; float* sb = S + S_SB;  float* ctx = S + S_CTX;
    float4* rel4 = (float4*)(S + S_REL4);
    float* msk = S + S_MSK;  float* inv = S + S_INV;

    const float kw0 = sm[O_KPW + lane*3+0], kw1 = sm[O_KPW + lane*3+1],
                kw2 = sm[O_KPW + lane*3+2], kb_ = sm[O_KPB + lane];

    const int step = gridDim.x * NSLOT;

    // --- prefetch state (consumed next iteration) ---
    float nc0, nc1, nc2, nmv = 0.f, nvx = 0.f, nvy = 0.f, nvz = 0.f;
    int nvi = 0;
    {
        int qn = blockIdx.x * NSLOT + slot;
        int qc_ = (qn < m) ? qn : 0;
        nc0 = __ldg(&qcoord[qc_*3+0]);
        nc1 = __ldg(&qcoord[qc_*3+1]);
        nc2 = __ldg(&qcoord[qc_*3+2]);
        if (lane < K_) {
            const int idx = qc_ * K_ + lane;
            nvi = __ldg(&kidx[idx]);
            if (mode == 0)      nmv = ((const unsigned char*)kmask)[idx] ? 1.f : 0.f;
            else if (mode == 1) nmv = ((const int*)kmask)[idx] ? 1.f : 0.f;
            else                nmv = (((const float*)kmask)[idx] != 0.f) ? 1.f : 0.f;
            nvx = __ldg(&vcoord[nvi*3+0]);
            nvy = __ldg(&vcoord[nvi*3+1]);
            nvz = __ldg(&vcoord[nvi*3+2]);
        }
    }

    for (int q0 = blockIdx.x * NSLOT; q0 < m; q0 += step) {
        const int q = q0 + slot;
        const bool valid = (q < m);

        if (valid) {   // P01: consume prefetched data
            const float c0 = nc0, c1 = nc1, c2 = nc2;
            if (lane < K_) {
                msk[lane] = nmv;
                float4 r;
                r.x = nvx - c0; r.y = nvy - c1; r.z = nvz - c2;
                r.w = __int_as_float(nvi);
                rel4[lane] = r;
            }
            float t = sm[O_QPB + lane];
            t = fmaf(sm[O_QPW + lane*3+0], c0, t);
            t = fmaf(sm[O_QPW + lane*3+1], c1, t);
            t = fmaf(sm[O_QPW + lane*3+2], c2, t);
            qin_s[lane] = fmaxf(t, 0.f);
        }
        {   // prefetch next query's data (in flight across P2..P7)
            int qn = q + step;
            int qc_ = (qn < m) ? qn : 0;
            nc0 = __ldg(&qcoord[qc_*3+0]);
            nc1 = __ldg(&qcoord[qc_*3+1]);
            nc2 = __ldg(&qcoord[qc_*3+2]);
            if (lane < K_) {
                const int idx = qc_ * K_ + lane;
                nvi = __ldg(&kidx[idx]);
                if (mode == 0)      nmv = ((const unsigned char*)kmask)[idx] ? 1.f : 0.f;
                else if (mode == 1) nmv = ((const int*)kmask)[idx] ? 1.f : 0.f;
                else                nmv = (((const float*)kmask)[idx] != 0.f) ? 1.f : 0.f;
                nvx = __ldg(&vcoord[nvi*3+0]);
                nvy = __ldg(&vcoord[nvi*3+1]);
                nvz = __ldg(&vcoord[nvi*3+2]);
            }
        }
        BAR64(bid);

        if (valid) {   // P2: q = (q_in @ wq^T + bq) * d^-0.5
            float acc = sm[O_BQ + lane];
            #pragma unroll
            for (int cp = 0; cp < 64; cp += 4) {
                float4 a = *(const float4*)&qin_s[cp];
                acc = fmaf(a.x, sm[O_WQT + (cp+0)*64 + lane], acc);
                acc = fmaf(a.y, sm[O_WQT + (cp+1)*64 + lane], acc);
                acc = fmaf(a.z, sm[O_WQT + (cp+2)*64 + lane], acc);
                acc = fmaf(a.w, sm[O_WQT + (cp+3)*64 + lane], acc);
            }
            qv_s[lane] = acc * 0.25f;
        }
        BAR64(bid);

        if (valid) {   // P3: u[h] = wk_h^T @ q_h ; gather k_in (batched LDG)
            #pragma unroll
            for (int h = 0; h < 4; h++) {
                float acc = 0.f;
                #pragma unroll
                for (int j4 = 0; j4 < 4; j4++) {
                    float4 qv = *(const float4*)&qv_s[h*16 + j4*4];
                    acc = fmaf(sm[O_WK + (h*16+j4*4+0)*64 + lane], qv.x, acc);
                    acc = fmaf(sm[O_WK + (h*16+j4*4+1)*64 + lane], qv.y, acc);
                    acc = fmaf(sm[O_WK + (h*16+j4*4+2)*64 + lane], qv.z, acc);
                    acc = fmaf(sm[O_WK + (h*16+j4*4+3)*64 + lane], qv.w, acc);
                }
                u_s[h*64 + lane] = acc;
            }
            #pragma unroll
            for (int kb = 0; kb < K_; kb += 16) {
                float4 r4[16];
                #pragma unroll
                for (int j = 0; j < 16; j++) r4[j] = rel4[kb+j];
                float fv[16];
                #pragma unroll
                for (int j = 0; j < 16; j++)
                    fv[j] = __ldg(&vf[__float_as_int(r4[j].w) * 64 + lane]);
                #pragma unroll
                for (int j = 0; j < 16; j++) {
                    float kp = kb_;
                    kp = fmaf(kw0, r4[j].x, kp);
                    kp = fmaf(kw1, r4[j].y, kp);
                    kp = fmaf(kw2, r4[j].z, kp);
                    kin[(kb+j)*KSTR + lane] = fv[j] + fmaxf(kp, 0.f);
                }
            }
        }
        BAR64(bid);

        if (valid && lane < K_) {   // P4: scores — lane = key, all 4 heads
            const int k = lane;
            const float2* kr = (const float2*)&kin[k*KSTR];
            const float4* u4 = (const float4*)u_s;
            float4 acc = make_float4(0.f, 0.f, 0.f, 0.f);
            #pragma unroll 4
            for (int c4 = 0; c4 < 16; c4++) {
                float2 ka = kr[2*c4], kc = kr[2*c4+1];
                float4 a0 = u4[c4], a1 = u4[16+c4], a2 = u4[32+c4], a3 = u4[48+c4];
                acc.x = fmaf(ka.x,a0.x, fmaf(ka.y,a0.y, fmaf(kc.x,a0.z, fmaf(kc.y,a0.w, acc.x))));
                acc.y = fmaf(ka.x,a1.x, fmaf(ka.y,a1.y, fmaf(kc.x,a1.z, fmaf(kc.y,a1.w, acc.y))));
                acc.z = fmaf(ka.x,a2.x, fmaf(ka.y,a2.y, fmaf(kc.x,a2.z, fmaf(kc.y,a2.w, acc.z))));
                acc.w = fmaf(ka.x,a3.x, fmaf(ka.y,a3.y, fmaf(kc.x,a3.z, fmaf(kc.y,a3.w, acc.w))));
            }
            if (msk[k] != 0.f) acc = make_float4(-1e9f, -1e9f, -1e9f, -1e9f);
            *(float4*)&sb[k*4] = acc;
        }
        BAR64(bid);

        if (valid) {   // P5: softmax over k per head (16 lanes per head)
            const int h = lane >> 4, j = lane & 15;
            float v0 = sb[j*4+h], v1 = sb[(j+16)*4+h], v2 = sb[(j+32)*4+h];
            float mx = fmaxf(v0, fmaxf(v1, v2));
            #pragma unroll
            for (int off = 8; off; off >>= 1)
                mx = fmaxf(mx, __shfl_xor_sync(0xffffffffu, mx, off));
            float e0 = __expf(v0-mx), e1 = __expf(v1-mx), e2 = __expf(v2-mx);
            sb[j*4+h] = e0; sb[(j+16)*4+h] = e1; sb[(j+32)*4+h] = e2;
            float s = e0 + e1 + e2;
            #pragma unroll
            for (int off = 8; off; off >>= 1)
                s += __shfl_xor_sync(0xffffffffu, s, off);
            if (j == 0) inv[h] = 1.0f / s;
        }
        BAR64(bid);

        if (valid) {   // P6: ctx[h,c] = sum_k a[h,k] k_in[k,c]
            float a0=0.f, a1=0.f, a2=0.f, a3=0.f;
            #pragma unroll 8
            for (int k = 0; k < K_; k++) {
                float4 e = *(const float4*)&sb[k*4];
                float kv = kin[k*KSTR + lane];
                a0 = fmaf(e.x, kv, a0); a1 = fmaf(e.y, kv, a1);
                a2 = fmaf(e.z, kv, a2); a3 = fmaf(e.w, kv, a3);
            }
            ctx[0*CTXSTR+lane] = a0*inv[0]; ctx[1*CTXSTR+lane] = a1*inv[1];
            ctx[2*CTXSTR+lane] = a2*inv[2]; ctx[3*CTXSTR+lane] = a3*inv[3];
        }
        BAR64(bid);

        if (valid) {   // P7: o = ctx @ wv^T + bv -> global
            const float4* cr4 = (const float4*)(ctx + (lane >> 4) * CTXSTR);
            float acc = sm[O_BV + lane];
            #pragma unroll 4
            for (int c4 = 0; c4 < 16; c4++) {
                float4 cv = cr4[c4];
                acc = fmaf(cv.x, sm[O_WVT + (c4*4+0)*64 + lane], acc);
                acc = fmaf(cv.y, sm[O_WVT + (c4*4+1)*64 + lane], acc);
                acc = fmaf(cv.z, sm[O_WVT + (c4*4+2)*64 + lane], acc);
                acc = fmaf(cv.w, sm[O_WVT + (c4*4+3)*64 + lane], acc);
            }
            g_obuf[q*64 + lane] = acc;
        }
    }
}

// ============================================================================
// Kernel 2: out_proj + FFN + BN1 + output layer + BN2 + ReLU
// 4 groups x 128 threads (c, half), 8 queries per group per tile.
// h: 2f x 8q register tile; x: f-split across halves with smem combine.
// ============================================================================
__global__ __launch_bounds__(512, 1) void ffn_kernel(
    const float* __restrict__ opw, const float* __restrict__ opb,
    const float* __restrict__ w1,  const float* __restrict__ b1,
    const float* __restrict__ w2,  const float* __restrict__ b2,
    const float* __restrict__ ng,  const float* __restrict__ nb,
    const float* __restrict__ nm,  const float* __restrict__ nv,
    const float* __restrict__ ow,  const float* __restrict__ ob,
    const float* __restrict__ g2,  const float* __restrict__ b2n,
    const float* __restrict__ m2,  const float* __restrict__ v2,
    float* __restrict__ out, int m, long long out_size)
{
    extern __shared__ float sm[];
    const int tid = threadIdx.x;

    for (long long i = (long long)m * 64 + (long long)blockIdx.x * blockDim.x + tid;
         i < out_size; i += (long long)gridDim.x * blockDim.x)
        out[i] = 0.f;

    for (int i = tid; i < 4096; i += 512) {
        int c = i & 63, cp = i >> 6;
        sm[Q_WOT  + i] = opw[c*64 + cp];
        sm[Q_WOUT + i] = ow[c*64 + cp];
    }
    for (int i = tid; i < 16384; i += 512) {
        sm[Q_W1T + i] = w1[(i & 255)*64 + (i >> 8)];
        sm[Q_W2T + i] = w2[(i & 63)*256 + (i >> 6)];
    }
    if (tid < 64) {
        sm[Q_BO + tid] = opb[tid];
        sm[Q_B2 + tid] = b2[tid];
        sm[Q_OUTB + tid] = ob[tid];
        float s1 = ng[tid] * rsqrtf(nv[tid] + 1e-5f);
        sm[Q_BN1S + tid] = s1;
        sm[Q_BN1T + tid] = nb[tid] - nm[tid] * s1;
        float s2 = g2[tid] * rsqrtf(v2[tid] + 1e-5f);
        sm[Q_BN2S + tid] = s2;
        sm[Q_BN2T + tid] = b2n[tid] - m2[tid] * s2;
    }
    if (tid < 256) sm[Q_B1 + tid] = b1[tid];
    __syncthreads();

    const int g = tid >> 7;          // group 0..3
    const int t = tid & 127;
    const int c = t & 63;
    const int half = t >> 6;         // 0/1
    const int bid = g + 1;
    const int jb = half * 4;         // query sub-range for att/y
    float* G    = sm + Q_GRP + g * GRP_FL;
    float* o8   = G;                 // 512 floats; later xp (partial x)
    float* att8 = G + 512;           // 512
    float* h8   = G + 1024;          // 2048; first 512 reused as xs

    const float bo_ = sm[Q_BO + c];
    const float bb2 = sm[Q_B2 + c];
    const float s1 = sm[Q_BN1S + c], t1 = sm[Q_BN1T + c];
    const float obc = sm[Q_OUTB + c], s2 = sm[Q_BN2S + c], t2 = sm[Q_BN2T + c];
    const int f0 = half * 128 + c, f1 = f0 + 64;
    const float b1a = sm[Q_B1 + f0], b1b = sm[Q_B1 + f1];

    for (int qb = blockIdx.x * 32; qb < m; qb += gridDim.x * 32) {
        const int qg = qb + g * 8;

        // 1. stage o tile: thread loads its 4 queries (jb..jb+3) for channel c
        float4 ov;
        ov.x = (qg+jb+0 < m) ? g_obuf[(qg+jb+0)*64 + c] : 0.f;
        ov.y = (qg+jb+1 < m) ? g_obuf[(qg+jb+1)*64 + c] : 0.f;
        ov.z = (qg+jb+2 < m) ? g_obuf[(qg+jb+2)*64 + c] : 0.f;
        ov.w = (qg+jb+3 < m) ? g_obuf[(qg+jb+3)*64 + c] : 0.f;
        *(float4*)&o8[c*8 + jb] = ov;
        BAR128(bid);

        // 2. attend = o @ Wo^T + bo  (4 queries per thread)
        float4 att = make_float4(bo_, bo_, bo_, bo_);
        #pragma unroll 8
        for (int cp = 0; cp < 64; cp++) {
            float w = sm[Q_WOT + cp*64 + c];
            float4 a = *(const float4*)&o8[cp*8 + jb];
            att.x = fmaf(a.x,w,att.x); att.y = fmaf(a.y,w,att.y);
            att.z = fmaf(a.z,w,att.z); att.w = fmaf(a.w,w,att.w);
        }
        *(float4*)&att8[c*8 + jb] = att;
        BAR128(bid);

        // 3. hidden: thread computes rows f0,f1 for ALL 8 queries (2f x 8q tile)
        float h0[8], h1[8];
        #pragma unroll
        for (int j = 0; j < 8; j++) { h0[j] = b1a; h1[j] = b1b; }
        #pragma unroll 4
        for (int cp = 0; cp < 64; cp++) {
            float w0 = sm[Q_W1T + cp*256 + f0];
            float w1 = sm[Q_W1T + cp*256 + f1];
            float4 alo = *(const float4*)&att8[cp*8];
            float4 ahi = *(const float4*)&att8[cp*8+4];
            h0[0]=fmaf(alo.x,w0,h0[0]); h0[1]=fmaf(alo.y,w0,h0[1]);
            h0[2]=fmaf(alo.z,w0,h0[2]); h0[3]=fmaf(alo.w,w0,h0[3]);
            h0[4]=fmaf(ahi.x,w0,h0[4]); h0[5]=fmaf(ahi.y,w0,h0[5]);
            h0[6]=fmaf(ahi.z,w0,h0[6]); h0[7]=fmaf(ahi.w,w0,h0[7]);
            h1[0]=fmaf(alo.x,w1,h1[0]); h1[1]=fmaf(alo.y,w1,h1[1]);
            h1[2]=fmaf(alo.z,w1,h1[2]); h1[3]=fmaf(alo.w,w1,h1[3]);
            h1[4]=fmaf(ahi.x,w1,h1[4]); h1[5]=fmaf(ahi.y,w1,h1[5]);
            h1[6]=fmaf(ahi.z,w1,h1[6]); h1[7]=fmaf(ahi.w,w1,h1[7]);
        }
        #pragma unroll
        for (int j = 0; j < 8; j++) { h0[j] = fmaxf(h0[j],0.f); h1[j] = fmaxf(h1[j],0.f); }
        *(float4*)&h8[f0*8]   = make_float4(h0[0],h0[1],h0[2],h0[3]);
        *(float4*)&h8[f0*8+4] = make_float4(h0[4],h0[5],h0[6],h0[7]);
        *(float4*)&h8[f1*8]   = make_float4(h1[0],h1[1],h1[2],h1[3]);
        *(float4*)&h8[f1*8+4] = make_float4(h1[4],h1[5],h1[6],h1[7]);
        BAR128(bid);

        // 4. x = attend + hidden @ W2^T + b2 — f-split across halves, 8q/thread
        float x[8];
        if (half == 0) {
            float4 alo = *(const float4*)&att8[c*8];
            float4 ahi = *(const float4*)&att8[c*8+4];
            x[0]=alo.x+bb2; x[1]=alo.y+bb2; x[2]=alo.z+bb2; x[3]=alo.w+bb2;
            x[4]=ahi.x+bb2; x[5]=ahi.y+bb2; x[6]=ahi.z+bb2; x[7]=ahi.w+bb2;
        } else {
            #pragma unroll
            for (int j = 0; j < 8; j++) x[j] = 0.f;
        }
        {
            const int fb = half * 128;
            #pragma unroll 4
            for (int fl = 0; fl < 128; fl++) {
                const int f = fb + fl;
                float w = sm[Q_W2T + f*64 + c];
                float4 hlo = *(const float4*)&h8[f*8];
                float4 hhi = *(const float4*)&h8[f*8+4];
                x[0]=fmaf(hlo.x,w,x[0]); x[1]=fmaf(hlo.y,w,x[1]);
                x[2]=fmaf(hlo.z,w,x[2]); x[3]=fmaf(hlo.w,w,x[3]);
                x[4]=fmaf(hhi.x,w,x[4]); x[5]=fmaf(hhi.y,w,x[5]);
                x[6]=fmaf(hhi.z,w,x[6]); x[7]=fmaf(hhi.w,w,x[7]);
            }
        }
        if (half == 1) {   // store partials into o8 region (dead after step 2)
            *(float4*)&o8[c*8]   = make_float4(x[0],x[1],x[2],x[3]);
            *(float4*)&o8[c*8+4] = make_float4(x[4],x[5],x[6],x[7]);
        }
        BAR128(bid);
        if (half == 0) {   // combine + BN1, store xs into h8 region (dead)
            float4 plo = *(const float4*)&o8[c*8];
            float4 phi = *(const float4*)&o8[c*8+4];
            x[0]+=plo.x; x[1]+=plo.y; x[2]+=plo.z; x[3]+=plo.w;
            x[4]+=phi.x; x[5]+=phi.y; x[6]+=phi.z; x[7]+=phi.w;
            #pragma unroll
            for (int j = 0; j < 8; j++) x[j] = fmaf(x[j], s1, t1);
            *(float4*)&h8[c*8]   = make_float4(x[0],x[1],x[2],x[3]);
            *(float4*)&h8[c*8+4] = make_float4(x[4],x[5],x[6],x[7]);
        }
        BAR128(bid);

        // 5. y = relu(BN2(x @ Wout^T + ob)) — 4 queries per thread
        float4 y = make_float4(0.f,0.f,0.f,0.f);
        #pragma unroll 8
        for (int cp = 0; cp < 64; cp++) {
            float w = sm[Q_WOUT + cp*64 + c];
            float4 xv = *(const float4*)&h8[cp*8 + jb];
            y.x = fmaf(xv.x,w,y.x); y.y = fmaf(xv.y,w,y.y);
            y.z = fmaf(xv.z,w,y.z); y.w = fmaf(xv.w,w,y.w);
        }
        y.x = fmaxf(fmaf(y.x+obc, s2, t2), 0.f);
        y.y = fmaxf(fmaf(y.y+obc, s2, t2), 0.f);
        y.z = fmaxf(fmaf(y.z+obc, s2, t2), 0.f);
        y.w = fmaxf(fmaf(y.w+obc, s2, t2), 0.f);
        if (qg+jb+0 < m) out[(qg+jb+0)*64 + c] = y.x;
        if (qg+jb+1 < m) out[(qg+jb+1)*64 + c] = y.y;
        if (qg+jb+2 < m) out[(qg+jb+2)*64 + c] = y.z;
        if (qg+jb+3 < m) out[(qg+jb+3)*64 + c] = y.w;
        BAR128(bid);   // protect o8/att8/h8 before next tile
    }
}

extern "C" void kernel_launch(void* const* d_in, const int* in_sizes, int n_in,
                              void* d_out, int out_size)
{
    const float* vf  = (const float*)d_in[0];
    const float* vc  = (const float*)d_in[1];
    const float* qc  = (const float*)d_in[2];
    const int*   ki  = (const int*)d_in[3];
    const void*  km  = d_in[4];
    const float* qpw = (const float*)d_in[5];
    const float* qpb = (const float*)d_in[6];
    const float* kpw = (const float*)d_in[7];
    const float* kpb = (const float*)d_in[8];
    const float* ipw = (const float*)d_in[9];
    const float* ipb = (const float*)d_in[10];
    const float* opw = (const float*)d_in[11];
    const float* opb = (const float*)d_in[12];
    const float* w1  = (const float*)d_in[13];
    const float* b1  = (const float*)d_in[14];
    const float* w2  = (const float*)d_in[15];
    const float* b2  = (const float*)d_in[16];
    const float* ng  = (const float*)d_in[17];
    const float* nb  = (const float*)d_in[18];
    const float* nm  = (const float*)d_in[19];
    const float* nv  = (const float*)d_in[20];
    const float* ow  = (const float*)d_in[21];
    const float* ob  = (const float*)d_in[22];
    const float* g2  = (const float*)d_in[23];
    const float* b2n = (const float*)d_in[24];
    const float* m2  = (const float*)d_in[25];
    const float* v2  = (const float*)d_in[26];

    int m = in_sizes[2] / 3;
    if (m > MQ_MAX) m = MQ_MAX;

    cudaFuncSetAttribute(attn_kernel, cudaFuncAttributeMaxDynamicSharedMemorySize, SMEM1_BYTES);
    cudaFuncSetAttribute(ffn_kernel, cudaFuncAttributeMaxDynamicSharedMemorySize, SMEM2_BYTES);

    attn_kernel<<<148, 512, SMEM1_BYTES>>>(vf, vc, qc, ki, km, qpw, qpb, kpw, kpb, ipw, ipb, m);
    ffn_kernel<<<148, 512, SMEM2_BYTES>>>(opw, opb, w1, b1, w2, b2, ng, nb, nm, nv,
                                          ow, ob, g2, b2n, m2, v2, (float*)d_out, m,
                                          (long long)out_size);
}